// round 3
// baseline (speedup 1.0000x reference)
#include <cuda_runtime.h>
#include <math.h>

#define B_   8
#define R_   10
#define NN   80
#define CS   2048
#define CF   256
#define NS   8
#define NF   32
#define HH   16
#define WW   16
#define HW   256
#define CC   2304
#define RD   1024
#define HD   512
#define NCLS 60
#define KC   4608

// ---------------- scratch ----------------
__device__ __align__(128) float g_tslow[(size_t)B_*NS*HW*CS];
__device__ __align__(128) float g_tfast[(size_t)B_*NF*HW*CF];
__device__ __align__(128) float g_mean [(size_t)B_*CC*HW];
__device__ __align__(128) float g_pool [(size_t)NN*49*CC];
__device__ __align__(128) float g_actor[(size_t)NN*RD];
__device__ __align__(128) float g_gfeat[(size_t)B_*RD*HW];
__device__ __align__(128) float g_gbase[(size_t)B_*HD*HW];
__device__ __align__(128) float g_av   [(size_t)HD*NN];
__device__ __align__(128) float g_x1   [(size_t)NN*HD*HW];
__device__ __align__(128) float g_colE [(size_t)NN*196*KC];
__device__ __align__(128) float g_x2   [(size_t)NN*HD*196];
__device__ __align__(128) float g_x    [(size_t)NN*HD*49];
__device__ __align__(128) float g_colF [(size_t)NN*49*KC];
__device__ __align__(128) float g_q    [(size_t)NN*HD*49];
__device__ __align__(128) float g_k    [(size_t)NN*HD*49];
__device__ __align__(128) float g_v    [(size_t)NN*HD*49];
__device__ __align__(128) float g_virt [(size_t)NN*HD*49];
__device__ __align__(128) float g_mu   [NN];
__device__ __align__(128) float g_rstd [NN];
__device__ __align__(128) float g_ho   [(size_t)NN*HD];
__device__ __align__(128) float g_a1   [(size_t)HD*NN];

// -------- transpose [b][C][T][p] -> [b][t][p][C] --------
__global__ void k_transpose(const float* __restrict__ src, float* __restrict__ dst,
                            int C, int T) {
    __shared__ float tile[32][33];
    int bt = blockIdx.z;
    int b = bt / T, t = bt - b * T;
    int c0 = blockIdx.x << 5, p0 = blockIdx.y << 5;
    int x = threadIdx.x;
    #pragma unroll
    for (int r = 0; r < 4; r++) {
        int yy = threadIdx.y + r * 8;
        tile[yy][x] = src[((size_t)(b * C + c0 + yy) * T + t) * HW + p0 + x];
    }
    __syncthreads();
    #pragma unroll
    for (int r = 0; r < 4; r++) {
        int yy = threadIdx.y + r * 8;
        dst[((size_t)(b * T + t) * HW + p0 + yy) * C + c0 + x] = tile[x][yy];
    }
}

// -------- temporal means, concat slow||fast --------
__global__ void k_mean(const float* __restrict__ slow, const float* __restrict__ fast,
                       float* __restrict__ mean) {
    int i = blockIdx.x * 256 + threadIdx.x;
    if (i >= B_ * CC * HW) return;
    int p = i & 255;
    int t2 = i >> 8;
    int c = t2 % CC;
    int b = t2 / CC;
    float s = 0.f;
    if (c < CS) {
        const float* base = slow + ((size_t)(b * CS + c) * NS) * HW + p;
        #pragma unroll
        for (int t = 0; t < NS; t++) s += base[t * HW];
        s *= (1.f / NS);
    } else {
        const float* base = fast + ((size_t)(b * CF + (c - CS)) * NF) * HW + p;
        #pragma unroll
        for (int t = 0; t < NF; t++) s += base[t * HW];
        s *= (1.f / NF);
    }
    mean[i] = s;
}

// -------- roi-align bilinear bin accumulation (channel-last feat) --------
template<int NCH>
__device__ __forceinline__ void accum_bin(float acc[NCH], const float* __restrict__ fbase,
                                          int C, int c0, const float* __restrict__ r5,
                                          int py, int px) {
    float rx1 = r5[1] * WW, ry1 = r5[2] * HH, rx2 = r5[3] * WW, ry2 = r5[4] * HH;
    float roi_w = fmaxf(rx2 - rx1, 1.f), roi_h = fmaxf(ry2 - ry1, 1.f);
    float bw = roi_w * (1.f / 7.f), bh = roi_h * (1.f / 7.f);
    float gw = ceilf(bw), gh = ceilf(bh);
    int igh = min((int)gh, 3), igw = min((int)gw, 3);
    float minv = 1.f / (gh * gw);
    for (int iy = 0; iy < igh; iy++) {
        float yy = ry1 + py * bh + (iy + 0.5f) * bh / gh;
        for (int ix = 0; ix < igw; ix++) {
            float xx = rx1 + px * bw + (ix + 0.5f) * bw / gw;
            if (!(yy > -1.f && yy < (float)HH && xx > -1.f && xx < (float)WW)) continue;
            float y = fminf(fmaxf(yy, 0.f), HH - 1.f);
            float x = fminf(fmaxf(xx, 0.f), WW - 1.f);
            int y0 = (int)floorf(y), x0 = (int)floorf(x);
            int y1i = min(y0 + 1, HH - 1), x1i = min(x0 + 1, WW - 1);
            float ly = y - (float)y0, lx = x - (float)x0;
            float hy = 1.f - ly, hx = 1.f - lx;
            float w00 = hy * hx * minv, w01 = hy * lx * minv;
            float w10 = ly * hx * minv, w11 = ly * lx * minv;
            const float* p00 = fbase + (size_t)(y0 * WW + x0) * C + c0;
            const float* p01 = fbase + (size_t)(y0 * WW + x1i) * C + c0;
            const float* p10 = fbase + (size_t)(y1i * WW + x0) * C + c0;
            const float* p11 = fbase + (size_t)(y1i * WW + x1i) * C + c0;
            #pragma unroll
            for (int j = 0; j < NCH; j++) {
                int off = j * 256;
                acc[j] += w00 * p00[off] + w01 * p01[off] + w10 * p10[off] + w11 * p11[off];
            }
        }
    }
}

// roi pooling fused with temporal mean over valid frames -> pool[n][s][2304]
__global__ void k_roipool(const float* __restrict__ rois, const float* __restrict__ tslow,
                          const float* __restrict__ tfast, float* __restrict__ pool) {
    int s = blockIdx.x, n = blockIdx.y;
    int py = s / 7, px = s - py * 7;
    int tid = threadIdx.x;
    size_t ob = ((size_t)n * 49 + s) * CC;

    float acc[8];
    #pragma unroll
    for (int j = 0; j < 8; j++) acc[j] = 0.f;
    int cnt = 0;
    for (int t = 0; t < NS; t++) {
        const float* r5 = rois + ((size_t)n * NF + (4 * t + 3)) * 5;
        if (r5[1] == 1.f && r5[2] == 1.f && r5[3] == 1.f && r5[4] == 1.f) continue;
        cnt++;
        int bi = (int)r5[0];
        accum_bin<8>(acc, tslow + (size_t)(bi * NS + t) * HW * CS, CS, tid, r5, py, px);
    }
    float sc = 1.f / (float)max(cnt, 1);
    #pragma unroll
    for (int j = 0; j < 8; j++) pool[ob + tid + j * 256] = acc[j] * sc;

    float accf[1] = {0.f};
    cnt = 0;
    for (int t = 0; t < NF; t++) {
        const float* r5 = rois + ((size_t)n * NF + t) * 5;
        if (r5[1] == 1.f && r5[2] == 1.f && r5[3] == 1.f && r5[4] == 1.f) continue;
        cnt++;
        int bi = (int)r5[0];
        accum_bin<1>(accf, tfast + (size_t)(bi * NF + t) * HW * CF, CF, tid, r5, py, px);
    }
    pool[ob + CS + tid] = accf[0] / (float)max(cnt, 1);
}

// -------- generic fp32 GEMM: C[z][M][S] = A[M][K] @ B[z] --------
// BT=true : B is Bt[z][S][K]; BT=false: B is B[z][K][S] (S==256 only)
// EPI: 0=store 1=relu 2=accumulate 3=row-max over S -> C[z][M] (needs gridDim.x==1)
template<int S, bool BT, int EPI>
__global__ __launch_bounds__(256) void k_gemm(
    const float* __restrict__ A, int lda, int aoff,
    const float* __restrict__ Bm, long bstride,
    float* __restrict__ C, long cstride, int K) {
    __shared__ float As[16][132];
    __shared__ float Bs[16][68];
    int s0 = blockIdx.x << 6;
    int m0 = blockIdx.y << 7;
    int batch = blockIdx.z;
    const float* Bb = Bm + (size_t)batch * bstride;
    int tid = threadIdx.x;
    int tx = tid & 15, ty = tid >> 4;
    int lm = tid >> 2;
    int lk = (tid & 3) << 2;
    const float* Arow0 = A + (size_t)(m0 + lm) * lda + aoff + lk;
    const float* Arow1 = Arow0 + (size_t)64 * lda;

    float acc[8][4];
    #pragma unroll
    for (int i = 0; i < 8; i++)
        #pragma unroll
        for (int j = 0; j < 4; j++) acc[i][j] = 0.f;

    for (int k0 = 0; k0 < K; k0 += 16) {
        float4 a0 = *(const float4*)(Arow0 + k0);
        float4 a1 = *(const float4*)(Arow1 + k0);
        As[lk + 0][lm] = a0.x; As[lk + 1][lm] = a0.y;
        As[lk + 2][lm] = a0.z; As[lk + 3][lm] = a0.w;
        As[lk + 0][lm + 64] = a1.x; As[lk + 1][lm + 64] = a1.y;
        As[lk + 2][lm + 64] = a1.z; As[lk + 3][lm + 64] = a1.w;
        if (BT) {
            int s = s0 + lm;
            float4 bv = make_float4(0.f, 0.f, 0.f, 0.f);
            if (s < S) bv = *(const float4*)(Bb + (size_t)s * K + k0 + lk);
            Bs[lk + 0][lm] = bv.x; Bs[lk + 1][lm] = bv.y;
            Bs[lk + 2][lm] = bv.z; Bs[lk + 3][lm] = bv.w;
        } else {
            int bk = tid >> 4;
            int bs = (tid & 15) << 2;
            float4 bv = *(const float4*)(Bb + (size_t)(k0 + bk) * S + s0 + bs);
            Bs[bk][bs] = bv.x; Bs[bk][bs + 1] = bv.y;
            Bs[bk][bs + 2] = bv.z; Bs[bk][bs + 3] = bv.w;
        }
        __syncthreads();
        #pragma unroll
        for (int kk = 0; kk < 16; kk++) {
            float a[8], b[4];
            #pragma unroll
            for (int i = 0; i < 8; i++) a[i] = As[kk][ty + (i << 4)];
            #pragma unroll
            for (int j = 0; j < 4; j++) b[j] = Bs[kk][tx + (j << 4)];
            #pragma unroll
            for (int i = 0; i < 8; i++)
                #pragma unroll
                for (int j = 0; j < 4; j++)
                    acc[i][j] = fmaf(a[i], b[j], acc[i][j]);
        }
        __syncthreads();
    }

    if (EPI == 3) {
        #pragma unroll
        for (int i = 0; i < 8; i++) {
            float mval = -3.4e38f;
            #pragma unroll
            for (int j = 0; j < 4; j++) {
                int sl = tx + (j << 4);
                if (s0 + sl < S) mval = fmaxf(mval, acc[i][j]);
            }
            #pragma unroll
            for (int off = 8; off; off >>= 1)
                mval = fmaxf(mval, __shfl_xor_sync(0xffffffffu, mval, off, 16));
            if (tx == 0) C[(size_t)batch * cstride + m0 + ty + (i << 4)] = mval;
        }
    } else {
        #pragma unroll
        for (int i = 0; i < 8; i++) {
            int m = m0 + ty + (i << 4);
            #pragma unroll
            for (int j = 0; j < 4; j++) {
                int sg = s0 + tx + (j << 4);
                if (sg < S) {
                    size_t idx = (size_t)batch * cstride + (size_t)m * S + sg;
                    float vv = acc[i][j];
                    if (EPI == 1) vv = fmaxf(vv, 0.f);
                    if (EPI == 2) vv += C[idx];
                    C[idx] = vv;
                }
            }
        }
    }
}

// -------- x1 = relu(gbase[b] + av broadcast) --------
__global__ void k_x1(const float* __restrict__ gbase, const float* __restrict__ av,
                     float* __restrict__ x1) {
    int i = blockIdx.x * 256 + threadIdx.x;
    if (i >= NN * HD * HW) return;
    int p = i & 255;
    int t = i >> 8;
    int c = t % HD;
    int n = t / HD;
    int b = n / R_;
    float v = gbase[((size_t)(b * HD + c)) * HW + p] + av[(size_t)c * NN + n];
    x1[i] = fmaxf(v, 0.f);
}

// -------- im2col 16x16 -> 14x14 (pad 0) --------
__global__ void k_im2col16(const float* __restrict__ x1, float* __restrict__ col) {
    int s = blockIdx.x, n = blockIdx.y;
    int sy = s / 14, sx = s - sy * 14;
    size_t ob = ((size_t)n * 196 + s) * KC;
    const float* xb = x1 + (size_t)n * HD * HW;
    for (int k = threadIdx.x; k < KC; k += 256) {
        int ic = k / 9, tap = k - ic * 9;
        int ky = tap / 3, kx = tap - ky * 3;
        col[ob + k] = xb[(size_t)ic * HW + (sy + ky) * 16 + sx + kx];
    }
}

// -------- maxpool 3x3 s2 p1 : 14x14 -> 7x7 --------
__global__ void k_maxpool(const float* __restrict__ x2, float* __restrict__ x) {
    int i = blockIdx.x * 256 + threadIdx.x;
    if (i >= NN * HD * 49) return;
    int p = i % 49;
    int t = i / 49;
    int py = p / 7, px = p - py * 7;
    float m = -3.4e38f;
    const float* base = x2 + (size_t)t * 196;
    #pragma unroll
    for (int ky = 0; ky < 3; ky++) {
        int y = 2 * py - 1 + ky;
        if (y < 0 || y >= 14) continue;
        #pragma unroll
        for (int kx = 0; kx < 3; kx++) {
            int xx = 2 * px - 1 + kx;
            if (xx < 0 || xx >= 14) continue;
            m = fmaxf(m, base[y * 14 + xx]);
        }
    }
    x[i] = m;
}

// -------- im2col 7x7 pad1 --------
__global__ void k_im2col7(const float* __restrict__ x, float* __restrict__ col) {
    int s = blockIdx.x, n = blockIdx.y;
    int sy = s / 7, sx = s - sy * 7;
    size_t ob = ((size_t)n * 49 + s) * KC;
    const float* xb = x + (size_t)n * HD * 49;
    for (int k = threadIdx.x; k < KC; k += 256) {
        int ic = k / 9, tap = k - ic * 9;
        int ky = tap / 3, kx = tap - ky * 3;
        int y = sy + ky - 1, xx = sx + kx - 1;
        float v = 0.f;
        if (y >= 0 && y < 7 && xx >= 0 && xx < 7)
            v = xb[(size_t)ic * 49 + y * 7 + xx];
        col[ob + k] = v;
    }
}

// -------- im2col 7x7 pad1 with fused LayerNorm + affine + relu --------
__global__ void k_im2col7_ln(const float* __restrict__ virt, const float* __restrict__ mu,
                             const float* __restrict__ rstd, const float* __restrict__ gg,
                             const float* __restrict__ gb, float* __restrict__ col) {
    int s = blockIdx.x, n = blockIdx.y;
    int sy = s / 7, sx = s - sy * 7;
    size_t ob = ((size_t)n * 49 + s) * KC;
    const float* vb = virt + (size_t)n * HD * 49;
    float m = mu[n], rs = rstd[n];
    for (int k = threadIdx.x; k < KC; k += 256) {
        int ic = k / 9, tap = k - ic * 9;
        int ky = tap / 3, kx = tap - ky * 3;
        int y = sy + ky - 1, xx = sx + kx - 1;
        float v = 0.f;
        if (y >= 0 && y < 7 && xx >= 0 && xx < 7) {
            float raw = vb[(size_t)ic * 49 + y * 7 + xx];
            v = fmaxf((raw - m) * rs * gg[ic] + gb[ic], 0.f);
        }
        col[ob + k] = v;
    }
}

// -------- attention per (batch, spatial position) --------
__global__ __launch_bounds__(512) void k_att(const float* __restrict__ q,
                                             const float* __restrict__ kk_,
                                             const float* __restrict__ v,
                                             float* __restrict__ virt) {
    __shared__ float sq[10][512];
    __shared__ float sk[10][512];
    __shared__ float satt[10][12];
    int bp = blockIdx.x;
    int b = bp / 49, p = bp - b * 49;
    int n0 = b * R_;
    int tid = threadIdx.x;
    #pragma unroll
    for (int i = 0; i < 10; i++) {
        sq[i][tid] = q  [((size_t)(n0 + i) * HD + tid) * 49 + p];
        sk[i][tid] = kk_[((size_t)(n0 + i) * HD + tid) * 49 + p];
    }
    __syncthreads();
    int warp = tid >> 5, lane = tid & 31;
    for (int pr = warp; pr < 100; pr += 16) {
        int i = pr / 10, j = pr - i * 10;
        float s = 0.f;
        #pragma unroll
        for (int c = lane; c < 512; c += 32) s += sq[i][c] * sk[j][c];
        #pragma unroll
        for (int off = 16; off; off >>= 1) s += __shfl_xor_sync(0xffffffffu, s, off);
        if (lane == 0) satt[i][j] = s * 0.04419417382415922f;  // 1/sqrt(512)
    }
    __syncthreads();
    if (tid < 10) {
        float mx = -3.4e38f;
        #pragma unroll
        for (int j = 0; j < 10; j++) mx = fmaxf(mx, satt[tid][j]);
        float e[10], sum = 0.f;
        #pragma unroll
        for (int j = 0; j < 10; j++) { e[j] = expf(satt[tid][j] - mx); sum += e[j]; }
        float inv = 1.f / sum;
        #pragma unroll
        for (int j = 0; j < 10; j++) satt[tid][j] = e[j] * inv;
    }
    __syncthreads();
    float vv[10];
    #pragma unroll
    for (int j = 0; j < 10; j++)
        vv[j] = v[((size_t)(n0 + j) * HD + tid) * 49 + p];
    #pragma unroll
    for (int i = 0; i < 10; i++) {
        float a = 0.f;
        #pragma unroll
        for (int j = 0; j < 10; j++) a = fmaf(satt[i][j], vv[j], a);
        virt[((size_t)(n0 + i) * HD + tid) * 49 + p] = a;
    }
}

// -------- LayerNorm stats per roi --------
__global__ void k_lnstats(const float* __restrict__ virt, float* __restrict__ mu,
                          float* __restrict__ rstd) {
    __shared__ float s1[512], s2[512];
    int n = blockIdx.x, tid = threadIdx.x;
    const float* b = virt + (size_t)n * HD * 49;
    float a = 0.f, qq = 0.f;
    for (int i = tid; i < HD * 49; i += 512) { float x = b[i]; a += x; qq += x * x; }
    s1[tid] = a; s2[tid] = qq;
    __syncthreads();
    for (int off = 256; off; off >>= 1) {
        if (tid < off) { s1[tid] += s1[tid + off]; s2[tid] += s2[tid + off]; }
        __syncthreads();
    }
    if (tid == 0) {
        float m = s1[0] * (1.f / 25088.f);
        mu[n] = m;
        rstd[n] = rsqrtf(s2[0] * (1.f / 25088.f) - m * m + 1e-5f);
    }
}

// -------- high_order = mean over 7x7 --------
__global__ void k_homean(const float* __restrict__ x, float* __restrict__ ho) {
    int i = blockIdx.x * 256 + threadIdx.x;
    if (i >= NN * HD) return;
    const float* b = x + (size_t)i * 49;
    float s = 0.f;
    #pragma unroll
    for (int p = 0; p < 49; p++) s += b[p];
    ho[i] = s * (1.f / 49.f);
}

// -------- final FC: out[n][o] --------
__global__ void k_final(const float* __restrict__ a1t, const float* __restrict__ ho,
                        const float* __restrict__ fc2, float* __restrict__ out) {
    int n = blockIdx.x, o = threadIdx.x;
    if (o >= NCLS) return;
    const float* w = fc2 + (size_t)o * 1024;
    float s = 0.f;
    for (int c = 0; c < HD; c++) s = fmaf(a1t[(size_t)c * NN + n], w[c], s);
    const float* h = ho + (size_t)n * HD;
    for (int c = 0; c < HD; c++) s = fmaf(h[c], w[512 + c], s);
    out[(size_t)n * NCLS + o] = s;
}

extern "C" void kernel_launch(void* const* d_in, const int* in_sizes, int n_in,
                              void* d_out, int out_size) {
    const float* feat_slow = (const float*)d_in[0];
    const float* feat_fast = (const float*)d_in[1];
    const float* rois      = (const float*)d_in[2];
    const float* w_reduce  = (const float*)d_in[6];
    const float* w_conv1   = (const float*)d_in[7];
    const float* w_conv2   = (const float*)d_in[8];
    const float* wq        = (const float*)d_in[9];
    const float* wk        = (const float*)d_in[10];
    const float* wv        = (const float*)d_in[11];
    const float* wm        = (const float*)d_in[12];
    const float* gn_g      = (const float*)d_in[13];
    const float* gn_b      = (const float*)d_in[14];
    const float* fc1_w     = (const float*)d_in[15];
    const float* fc2_w     = (const float*)d_in[16];
    float* out = (float*)d_out;

    float *p_tslow, *p_tfast, *p_mean, *p_pool, *p_actor, *p_gfeat, *p_gbase,
          *p_av, *p_x1, *p_colE, *p_x2, *p_x, *p_colF, *p_q, *p_k, *p_v,
          *p_virt, *p_mu, *p_rstd, *p_ho, *p_a1;
    cudaGetSymbolAddress((void**)&p_tslow, g_tslow);
    cudaGetSymbolAddress((void**)&p_tfast, g_tfast);
    cudaGetSymbolAddress((void**)&p_mean,  g_mean);
    cudaGetSymbolAddress((void**)&p_pool,  g_pool);
    cudaGetSymbolAddress((void**)&p_actor, g_actor);
    cudaGetSymbolAddress((void**)&p_gfeat, g_gfeat);
    cudaGetSymbolAddress((void**)&p_gbase, g_gbase);
    cudaGetSymbolAddress((void**)&p_av,    g_av);
    cudaGetSymbolAddress((void**)&p_x1,    g_x1);
    cudaGetSymbolAddress((void**)&p_colE,  g_colE);
    cudaGetSymbolAddress((void**)&p_x2,    g_x2);
    cudaGetSymbolAddress((void**)&p_x,     g_x);
    cudaGetSymbolAddress((void**)&p_colF,  g_colF);
    cudaGetSymbolAddress((void**)&p_q,     g_q);
    cudaGetSymbolAddress((void**)&p_k,     g_k);
    cudaGetSymbolAddress((void**)&p_v,     g_v);
    cudaGetSymbolAddress((void**)&p_virt,  g_virt);
    cudaGetSymbolAddress((void**)&p_mu,    g_mu);
    cudaGetSymbolAddress((void**)&p_rstd,  g_rstd);
    cudaGetSymbolAddress((void**)&p_ho,    g_ho);
    cudaGetSymbolAddress((void**)&p_a1,    g_a1);

    // 1. channel-last transposes
    k_transpose<<<dim3(CS / 32, 8, B_ * NS), dim3(32, 8)>>>(feat_slow, p_tslow, CS, NS);
    k_transpose<<<dim3(CF / 32, 8, B_ * NF), dim3(32, 8)>>>(feat_fast, p_tfast, CF, NF);
    // 2. temporal means
    k_mean<<<(B_ * CC * HW + 255) / 256, 256>>>(feat_slow, feat_fast, p_mean);
    // 3. roi pooling (+ temporal mean over valid frames)
    k_roipool<<<dim3(49, NN), 256>>>(rois, p_tslow, p_tfast, p_pool);
    // 4. reduce conv on pooled rois, fused spatial max -> actor[n][1024]
    k_gemm<49, true, 3><<<dim3(1, 8, NN), 256>>>(w_reduce, CC, 0, p_pool, (long)49 * CC,
                                                 p_actor, RD, CC);
    // 5. gfeat = reduce conv on temporal means
    k_gemm<256, false, 0><<<dim3(4, 8, B_), 256>>>(w_reduce, CC, 0, p_mean, (long)CC * HW,
                                                   p_gfeat, (long)RD * HW, CC);
    // 6. gbase[b] = W1_global @ gfeat[b]
    k_gemm<256, false, 0><<<dim3(4, 4, B_), 256>>>(w_conv1, 2 * RD, 0, p_gfeat,
                                                   (long)RD * HW, p_gbase, (long)HD * HW, RD);
    // 7. av[c][n] = W1_actor @ actor
    k_gemm<80, true, 0><<<dim3(2, 4, 1), 256>>>(w_conv1, 2 * RD, RD, p_actor, 0,
                                                p_av, 0, RD);
    // 8. x1 = relu(gbase + av)
    k_x1<<<(NN * HD * HW + 255) / 256, 256>>>(p_gbase, p_av, p_x1);
    // 9. conv2 (3x3 valid): im2col + GEMM(relu)
    k_im2col16<<<dim3(196, NN), 256>>>(p_x1, p_colE);
    k_gemm<196, true, 1><<<dim3(4, 4, NN), 256>>>(w_conv2, KC, 0, p_colE, (long)196 * KC,
                                                  p_x2, (long)HD * 196, KC);
    // 10. maxpool -> x [n][512][49]
    k_maxpool<<<(NN * HD * 49 + 255) / 256, 256>>>(p_x2, p_x);

    // 11. HR2O blocks
    for (int d = 0; d < 2; d++) {
        long woff = (long)d * HD * KC;
        k_im2col7<<<dim3(49, NN), 256>>>(p_x, p_colF);
        k_gemm<49, true, 0><<<dim3(1, 4, NN), 256>>>(wq + woff, KC, 0, p_colF,
                                                     (long)49 * KC, p_q, (long)HD * 49, KC);
        k_gemm<49, true, 0><<<dim3(1, 4, NN), 256>>>(wk + woff, KC, 0, p_colF,
                                                     (long)49 * KC, p_k, (long)HD * 49, KC);
        k_gemm<49, true, 0><<<dim3(1, 4, NN), 256>>>(wv + woff, KC, 0, p_colF,
                                                     (long)49 * KC, p_v, (long)HD * 49, KC);
        k_att<<<B_ * 49, 512>>>(p_q, p_k, p_v, p_virt);
        k_lnstats<<<NN, 512>>>(p_virt, p_mu, p_rstd);
        k_im2col7_ln<<<dim3(49, NN), 256>>>(p_virt, p_mu, p_rstd,
                                            gn_g + (long)d * HD, gn_b + (long)d * HD, p_colF);
        k_gemm<49, true, 2><<<dim3(1, 4, NN), 256>>>(wm + woff, KC, 0, p_colF,
                                                     (long)49 * KC, p_x, (long)HD * 49, KC);
    }

    // 12. high_order mean
    k_homean<<<(NN * HD + 255) / 256, 256>>>(p_x, p_ho);
    // 13. a1t[c][n] = relu(actor @ fc1^T)
    k_gemm<80, true, 1><<<dim3(2, 4, 1), 256>>>(fc1_w, RD, 0, p_actor, 0, p_a1, 0, RD);
    // 14. final FC
    k_final<<<NN, 64>>>(p_a1, p_ho, fc2_w, out);
}

// round 6
// speedup vs baseline: 2.7311x; 2.7311x over previous
#include <cuda_runtime.h>
#include <cuda_bf16.h>
#include <stdint.h>
#include <math.h>

#define B_   8
#define R_   10
#define NN   80
#define CS   2048
#define CF   256
#define NS   8
#define NF   32
#define HH   16
#define WW   16
#define HW   256
#define CC   2304
#define RD   1024
#define HD   512
#define NCLS 60
#define KC   4608

typedef __nv_bfloat16 bf;

// ---------------- scratch ----------------
__device__ __align__(128) float g_tslow[(size_t)B_*NS*HW*CS];
__device__ __align__(128) float g_tfast[(size_t)B_*NF*HW*CF];
__device__ __align__(128) bf    g_meanT_h[(size_t)B_*HW*CC];
__device__ __align__(128) bf    g_meanT_l[(size_t)B_*HW*CC];
__device__ __align__(128) bf    g_pool_h[(size_t)NN*49*CC];
__device__ __align__(128) bf    g_pool_l[(size_t)NN*49*CC];
__device__ __align__(128) float g_red  [(size_t)RD*3920];
__device__ __align__(128) float g_actor[(size_t)NN*RD];
__device__ __align__(128) bf    g_gf_h [(size_t)B_*HW*RD];
__device__ __align__(128) bf    g_gf_l [(size_t)B_*HW*RD];
__device__ __align__(128) float g_gbase[(size_t)B_*HD*HW];
__device__ __align__(128) float g_av   [(size_t)HD*NN];
__device__ __align__(128) float g_x1   [(size_t)NN*HD*HW];
__device__ __align__(128) bf    g_colE_h[(size_t)NN*196*KC];
__device__ __align__(128) bf    g_colE_l[(size_t)NN*196*KC];
__device__ __align__(128) float g_x2   [(size_t)NN*HD*196];
__device__ __align__(128) float g_x    [(size_t)NN*HD*49];
__device__ __align__(128) bf    g_colF_h[(size_t)NN*49*KC];
__device__ __align__(128) bf    g_colF_l[(size_t)NN*49*KC];
__device__ __align__(128) float g_qkv  [(size_t)3*NN*HD*49];
__device__ __align__(128) float g_virt [(size_t)NN*HD*49];
__device__ __align__(128) float g_mu   [NN];
__device__ __align__(128) float g_rstd [NN];
__device__ __align__(128) float g_ho   [(size_t)NN*HD];
__device__ __align__(128) float g_a1   [(size_t)HD*NN];
// split weights
__device__ __align__(128) bf g_wred_h[(size_t)RD*CC];
__device__ __align__(128) bf g_wred_l[(size_t)RD*CC];
__device__ __align__(128) bf g_wg_h  [(size_t)HD*RD];
__device__ __align__(128) bf g_wg_l  [(size_t)HD*RD];
__device__ __align__(128) bf g_wc2_h [(size_t)HD*KC];
__device__ __align__(128) bf g_wc2_l [(size_t)HD*KC];
__device__ __align__(128) bf g_wqkv_h[(size_t)2*3*HD*KC];
__device__ __align__(128) bf g_wqkv_l[(size_t)2*3*HD*KC];
__device__ __align__(128) bf g_wm2_h [(size_t)2*HD*KC];
__device__ __align__(128) bf g_wm2_l [(size_t)2*HD*KC];

__device__ __forceinline__ void splitf(float x, bf& h, bf& l) {
    h = __float2bfloat16(x);
    l = __float2bfloat16(x - __bfloat162float(h));
}

// -------- weight split (strided) --------
__global__ void k_splits(const float* __restrict__ src, int ld, int koff, int K,
                         long total, bf* __restrict__ h, bf* __restrict__ l) {
    long i = (long)blockIdx.x * 256 + threadIdx.x;
    if (i >= total) return;
    long r = i / K; int c = (int)(i - r * K);
    float x = src[r * ld + koff + c];
    splitf(x, h[i], l[i]);
}

// -------- transpose [b][C][T][p] -> [b][t][p][C] --------
__global__ void k_transpose(const float* __restrict__ src, float* __restrict__ dst,
                            int C, int T) {
    __shared__ float tile[32][33];
    int bt = blockIdx.z;
    int b = bt / T, t = bt - b * T;
    int c0 = blockIdx.x << 5, p0 = blockIdx.y << 5;
    int x = threadIdx.x;
    #pragma unroll
    for (int r = 0; r < 4; r++) {
        int yy = threadIdx.y + r * 8;
        tile[yy][x] = src[((size_t)(b * C + c0 + yy) * T + t) * HW + p0 + x];
    }
    __syncthreads();
    #pragma unroll
    for (int r = 0; r < 4; r++) {
        int yy = threadIdx.y + r * 8;
        dst[((size_t)(b * T + t) * HW + p0 + yy) * C + c0 + x] = tile[x][yy];
    }
}

// -------- temporal means -> channel-last bf16 split [b][p][CC] --------
__global__ void k_meansplit(const float* __restrict__ slow, const float* __restrict__ fast,
                            bf* __restrict__ mh, bf* __restrict__ ml) {
    __shared__ float tile[32][33];
    int b = blockIdx.z;
    int c0 = blockIdx.x << 5, p0 = blockIdx.y << 5;
    int x = threadIdx.x;
    #pragma unroll
    for (int r = 0; r < 4; r++) {
        int cy = threadIdx.y + r * 8;
        int c = c0 + cy;
        float s = 0.f;
        if (c < CS) {
            const float* base = slow + ((size_t)(b * CS + c) * NS) * HW + p0 + x;
            #pragma unroll
            for (int t = 0; t < NS; t++) s += base[t * HW];
            s *= (1.f / NS);
        } else {
            const float* base = fast + ((size_t)(b * CF + (c - CS)) * NF) * HW + p0 + x;
            #pragma unroll
            for (int t = 0; t < NF; t++) s += base[t * HW];
            s *= (1.f / NF);
        }
        tile[cy][x] = s;
    }
    __syncthreads();
    #pragma unroll
    for (int r = 0; r < 4; r++) {
        int py = threadIdx.y + r * 8;
        size_t o = (size_t)(b * 256 + p0 + py) * CC + c0 + x;
        splitf(tile[x][py], mh[o], ml[o]);
    }
}

// -------- roi-align bilinear --------
template<int NCH>
__device__ __forceinline__ void accum_bin(float acc[NCH], const float* __restrict__ fbase,
                                          int C, int c0, const float* __restrict__ r5,
                                          int py, int px) {
    float rx1 = r5[1] * WW, ry1 = r5[2] * HH, rx2 = r5[3] * WW, ry2 = r5[4] * HH;
    float roi_w = fmaxf(rx2 - rx1, 1.f), roi_h = fmaxf(ry2 - ry1, 1.f);
    float bw = roi_w * (1.f / 7.f), bh = roi_h * (1.f / 7.f);
    float gw = ceilf(bw), gh = ceilf(bh);
    int igh = min((int)gh, 3), igw = min((int)gw, 3);
    float minv = 1.f / (gh * gw);
    for (int iy = 0; iy < igh; iy++) {
        float yy = ry1 + py * bh + (iy + 0.5f) * bh / gh;
        for (int ix = 0; ix < igw; ix++) {
            float xx = rx1 + px * bw + (ix + 0.5f) * bw / gw;
            if (!(yy > -1.f && yy < (float)HH && xx > -1.f && xx < (float)WW)) continue;
            float y = fminf(fmaxf(yy, 0.f), HH - 1.f);
            float x = fminf(fmaxf(xx, 0.f), WW - 1.f);
            int y0 = (int)floorf(y), x0 = (int)floorf(x);
            int y1i = min(y0 + 1, HH - 1), x1i = min(x0 + 1, WW - 1);
            float ly = y - (float)y0, lx = x - (float)x0;
            float hy = 1.f - ly, hx = 1.f - lx;
            float w00 = hy * hx * minv, w01 = hy * lx * minv;
            float w10 = ly * hx * minv, w11 = ly * lx * minv;
            const float* p00 = fbase + (size_t)(y0 * WW + x0) * C + c0;
            const float* p01 = fbase + (size_t)(y0 * WW + x1i) * C + c0;
            const float* p10 = fbase + (size_t)(y1i * WW + x0) * C + c0;
            const float* p11 = fbase + (size_t)(y1i * WW + x1i) * C + c0;
            #pragma unroll
            for (int j = 0; j < NCH; j++) {
                int off = j * 256;
                acc[j] += w00 * p00[off] + w01 * p01[off] + w10 * p10[off] + w11 * p11[off];
            }
        }
    }
}

__global__ void k_roipool(const float* __restrict__ rois, const float* __restrict__ tslow,
                          const float* __restrict__ tfast,
                          bf* __restrict__ ph, bf* __restrict__ pl) {
    int s = blockIdx.x, n = blockIdx.y;
    int py = s / 7, px = s - py * 7;
    int tid = threadIdx.x;
    size_t ob = ((size_t)n * 49 + s) * CC;

    float acc[8];
    #pragma unroll
    for (int j = 0; j < 8; j++) acc[j] = 0.f;
    int cnt = 0;
    for (int t = 0; t < NS; t++) {
        const float* r5 = rois + ((size_t)n * NF + (4 * t + 3)) * 5;
        if (r5[1] == 1.f && r5[2] == 1.f && r5[3] == 1.f && r5[4] == 1.f) continue;
        cnt++;
        int bi = (int)r5[0];
        accum_bin<8>(acc, tslow + (size_t)(bi * NS + t) * HW * CS, CS, tid, r5, py, px);
    }
    float sc = 1.f / (float)max(cnt, 1);
    #pragma unroll
    for (int j = 0; j < 8; j++) {
        size_t o = ob + tid + j * 256;
        splitf(acc[j] * sc, ph[o], pl[o]);
    }

    float accf[1] = {0.f};
    cnt = 0;
    for (int t = 0; t < NF; t++) {
        const float* r5 = rois + ((size_t)n * NF + t) * 5;
        if (r5[1] == 1.f && r5[2] == 1.f && r5[3] == 1.f && r5[4] == 1.f) continue;
        cnt++;
        int bi = (int)r5[0];
        accum_bin<1>(accf, tfast + (size_t)(bi * NF + t) * HW * CF, CF, tid, r5, py, px);
    }
    size_t o = ob + CS + tid;
    splitf(accf[0] / (float)max(cnt, 1), ph[o], pl[o]);
}

// ================= tensor-core GEMM (bf16 3-term split, mma.sync m16n8k16) ======
__device__ __forceinline__ uint32_t s2u(const void* p) {
    return (uint32_t)__cvta_generic_to_shared(p);
}
__device__ __forceinline__ void cpa16(uint32_t s, const void* g, bool pred) {
    asm volatile("cp.async.cg.shared.global [%0], [%1], 16, %2;\n"
                 :: "r"(s), "l"(g), "r"(pred ? 16 : 0));
}
__device__ __forceinline__ void mma16816(float* c, const uint32_t* a, const uint32_t* b) {
    asm volatile(
        "mma.sync.aligned.m16n8k16.row.col.f32.bf16.bf16.f32 "
        "{%0,%1,%2,%3},{%4,%5,%6,%7},{%8,%9},{%0,%1,%2,%3};\n"
        : "+f"(c[0]), "+f"(c[1]), "+f"(c[2]), "+f"(c[3])
        : "r"(a[0]), "r"(a[1]), "r"(a[2]), "r"(a[3]), "r"(b[0]), "r"(b[1]));
}

// MODE 0: dst[m*N+col]
// MODE 1: qkv  -> dst[((m>>9)*NN + col/49)*HD*49 + (m&511)*49 + col%49]
// MODE 2: relu -> x2[(col/196*HD + m)*196 + col%196]
// MODE 3: acc  -> x [(col/49 *HD + m)*49  + col%49]
// MODE 4: bf16 split -> dsth/dstl[col*RD + m]
// MODE 5: gbase[((col>>8)*HD + m)*256 + (col&255)]
template<int MODE>
__global__ __launch_bounds__(256, 1) void k_tgemm(
    const bf* __restrict__ Ah, const bf* __restrict__ Al,
    const bf* __restrict__ Bh, const bf* __restrict__ Bl,
    int Ndim, int K,
    float* __restrict__ dst, bf* __restrict__ dsth, bf* __restrict__ dstl) {
    __shared__ uint32_t sAH[2][1024], sAL[2][1024], sBH[2][1024], sBL[2][1024];
    int tid = threadIdx.x;
    int bm0 = blockIdx.y << 7, bn0 = blockIdx.x << 7;
    int wid = tid >> 5, lane = tid & 31;
    int wm = wid >> 2, wn = wid & 3;
    int g = lane >> 2, tg = lane & 3;

    int lrow = tid >> 1, lchk = tid & 1;
    const bf* gAh = Ah + (size_t)(bm0 + lrow) * K + lchk * 8;
    const bf* gAl = Al + (size_t)(bm0 + lrow) * K + lchk * 8;
    bool bpred = (bn0 + lrow) < Ndim;
    long brow = bpred ? (bn0 + lrow) : (Ndim - 1);
    const bf* gBh = Bh + (size_t)brow * K + lchk * 8;
    const bf* gBl = Bl + (size_t)brow * K + lchk * 8;
    int soff = lrow * 8 + lchk * 4;

    float acc[4][4][4];
    #pragma unroll
    for (int i = 0; i < 4; i++)
        #pragma unroll
        for (int j = 0; j < 4; j++)
            #pragma unroll
            for (int r = 0; r < 4; r++) acc[i][j][r] = 0.f;

    int KT = K >> 4;
    cpa16(s2u(&sAH[0][soff]), gAh, true);
    cpa16(s2u(&sAL[0][soff]), gAl, true);
    cpa16(s2u(&sBH[0][soff]), gBh, bpred);
    cpa16(s2u(&sBL[0][soff]), gBl, bpred);
    asm volatile("cp.async.commit_group;\n");

    for (int kt = 0; kt < KT; kt++) {
        asm volatile("cp.async.wait_group 0;\n");
        __syncthreads();
        if (kt + 1 < KT) {
            int st = (kt + 1) & 1;
            size_t off = (size_t)(kt + 1) << 4;
            cpa16(s2u(&sAH[st][soff]), gAh + off, true);
            cpa16(s2u(&sAL[st][soff]), gAl + off, true);
            cpa16(s2u(&sBH[st][soff]), gBh + off, bpred);
            cpa16(s2u(&sBL[st][soff]), gBl + off, bpred);
            asm volatile("cp.async.commit_group;\n");
        }
        int st = kt & 1;
        const uint32_t* pAH = sAH[st];
        const uint32_t* pAL = sAL[st];
        const uint32_t* pBH = sBH[st];
        const uint32_t* pBL = sBL[st];
        uint32_t ah[4][4], al[4][4], bh[4][2], bl[4][2];
        #pragma unroll
        for (int mi = 0; mi < 4; mi++) {
            int r0 = wm * 64 + mi * 16 + g;
            ah[mi][0] = pAH[r0 * 8 + tg];
            ah[mi][1] = pAH[(r0 + 8) * 8 + tg];
            ah[mi][2] = pAH[r0 * 8 + tg + 4];
            ah[mi][3] = pAH[(r0 + 8) * 8 + tg + 4];
            al[mi][0] = pAL[r0 * 8 + tg];
            al[mi][1] = pAL[(r0 + 8) * 8 + tg];
            al[mi][2] = pAL[r0 * 8 + tg + 4];
            al[mi][3] = pAL[(r0 + 8) * 8 + tg + 4];
        }
        #pragma unroll
        for (int nj = 0; nj < 4; nj++) {
            int c0 = wn * 32 + nj * 8 + g;
            bh[nj][0] = pBH[c0 * 8 + tg];
            bh[nj][1] = pBH[c0 * 8 + tg + 4];
            bl[nj][0] = pBL[c0 * 8 + tg];
            bl[nj][1] = pBL[c0 * 8 + tg + 4];
        }
        #pragma unroll
        for (int mi = 0; mi < 4; mi++)
            #pragma unroll
            for (int nj = 0; nj < 4; nj++) {
                mma16816(acc[mi][nj], ah[mi], bh[nj]);
                mma16816(acc[mi][nj], ah[mi], bl[nj]);
                mma16816(acc[mi][nj], al[mi], bh[nj]);
            }
        __syncthreads();
    }

    #pragma unroll
    for (int mi = 0; mi < 4; mi++) {
        int rbase = bm0 + wm * 64 + mi * 16 + g;
        #pragma unroll
        for (int nj = 0; nj < 4; nj++) {
            int cbase = bn0 + wn * 32 + nj * 8 + tg * 2;
            #pragma unroll
            for (int ri = 0; ri < 4; ri++) {
                int row = rbase + ((ri >> 1) << 3);
                int col = cbase + (ri & 1);
                if (col >= Ndim) continue;
                float v = acc[mi][nj][ri];
                if (MODE == 0) {
                    dst[(size_t)row * Ndim + col] = v;
                } else if (MODE == 1) {
                    int which = row >> 9, c = row & 511;
                    int n = col / 49, s = col - n * 49;
                    dst[(((size_t)which * NN + n) * HD + c) * 49 + s] = v;
                } else if (MODE == 2) {
                    int n = col / 196, s = col - n * 196;
                    dst[((size_t)n * HD + row) * 196 + s] = fmaxf(v, 0.f);
                } else if (MODE == 3) {
                    int n = col / 49, s = col - n * 49;
                    size_t o = ((size_t)n * HD + row) * 49 + s;
                    dst[o] += v;
                } else if (MODE == 4) {
                    size_t o = (size_t)col * RD + row;
                    splitf(v, dsth[o], dstl[o]);
                } else if (MODE == 5) {
                    int b = col >> 8, p = col & 255;
                    dst[((size_t)b * HD + row) * 256 + p] = v;
                }
            }
        }
    }
}

// -------- actor = rowmax over 49 bins of g_red --------
__global__ void k_rowmax(const float* __restrict__ red, float* __restrict__ actor) {
    int i = blockIdx.x * 256 + threadIdx.x;
    if (i >= NN * RD) return;
    int m = i % RD, n = i / RD;
    const float* b = red + (size_t)m * 3920 + n * 49;
    float mx = -3.4e38f;
    #pragma unroll
    for (int s = 0; s < 49; s++) mx = fmaxf(mx, b[s]);
    actor[(size_t)n * RD + m] = mx;
}

// -------- small scalar GEMM (av / fc1) --------
template<int S, int EPI>
__global__ __launch_bounds__(256) void k_gemm(
    const float* __restrict__ A, int lda, int aoff,
    const float* __restrict__ Bm,
    float* __restrict__ C, int K) {
    __shared__ float As[16][132];
    __shared__ float Bs[16][68];
    int s0 = blockIdx.x << 6;
    int m0 = blockIdx.y << 7;
    int tid = threadIdx.x;
    int tx = tid & 15, ty = tid >> 4;
    int lm = tid >> 2;
    int lk = (tid & 3) << 2;
    const float* Arow0 = A + (size_t)(m0 + lm) * lda + aoff + lk;
    const float* Arow1 = Arow0 + (size_t)64 * lda;
    float acc[8][4];
    #pragma unroll
    for (int i = 0; i < 8; i++)
        #pragma unroll
        for (int j = 0; j < 4; j++) acc[i][j] = 0.f;
    for (int k0 = 0; k0 < K; k0 += 16) {
        float4 a0 = *(const float4*)(Arow0 + k0);
        float4 a1 = *(const float4*)(Arow1 + k0);
        As[lk + 0][lm] = a0.x; As[lk + 1][lm] = a0.y;
        As[lk + 2][lm] = a0.z; As[lk + 3][lm] = a0.w;
        As[lk + 0][lm + 64] = a1.x; As[lk + 1][lm + 64] = a1.y;
        As[lk + 2][lm + 64] = a1.z; As[lk + 3][lm + 64] = a1.w;
        int s = s0 + lm;
        float4 bv = make_float4(0.f, 0.f, 0.f, 0.f);
        if (s < S) bv = *(const float4*)(Bm + (size_t)s * K + k0 + lk);
        Bs[lk + 0][lm] = bv.x; Bs[lk + 1][lm] = bv.y;
        Bs[lk + 2][lm] = bv.z; Bs[lk + 3][lm] = bv.w;
        __syncthreads();
        #pragma unroll
        for (int kk = 0; kk < 16; kk++) {
            float a[8], b[4];
            #pragma unroll
            for (int i = 0; i < 8; i++) a[i] = As[kk][ty + (i << 4)];
            #pragma unroll
            for (int j = 0; j < 4; j++) b[j] = Bs[kk][tx + (j << 4)];
            #pragma unroll
            for (int i = 0; i < 8; i++)
                #pragma unroll
                for (int j = 0; j < 4; j++)
                    acc[i][j] = fmaf(a[i], b[j], acc[i][j]);
        }
        __syncthreads();
    }
    #pragma unroll
    for (int i = 0; i < 8; i++) {
        int m = m0 + ty + (i << 4);
        #pragma unroll
        for (int j = 0; j < 4; j++) {
            int sg = s0 + tx + (j << 4);
            if (sg < S) {
                float vv = acc[i][j];
                if (EPI == 1) vv = fmaxf(vv, 0.f);
                C[(size_t)m * S + sg] = vv;
            }
        }
    }
}

// -------- x1 = relu(gbase[b] + av) --------
__global__ void k_x1(const float* __restrict__ gbase, const float* __restrict__ av,
                     float* __restrict__ x1) {
    int i = blockIdx.x * 256 + threadIdx.x;
    if (i >= NN * HD * HW) return;
    int p = i & 255;
    int t = i >> 8;
    int c = t % HD;
    int n = t / HD;
    int b = n / R_;
    float v = gbase[((size_t)(b * HD + c)) * HW + p] + av[(size_t)c * NN + n];
    x1[i] = fmaxf(v, 0.f);
}

// -------- im2col 16x16 -> 14x14, bf16 split --------
__global__ void k_im2col16(const float* __restrict__ x1, bf* __restrict__ ch,
                           bf* __restrict__ cl) {
    int s = blockIdx.x, n = blockIdx.y;
    int sy = s / 14, sx = s - sy * 14;
    size_t ob = ((size_t)n * 196 + s) * KC;
    const float* xb = x1 + (size_t)n * HD * HW;
    for (int k = threadIdx.x; k < KC; k += 256) {
        int ic = k / 9, tap = k - ic * 9;
        int ky = tap / 3, kx = tap - ky * 3;
        splitf(xb[(size_t)ic * HW + (sy + ky) * 16 + sx + kx], ch[ob + k], cl[ob + k]);
    }
}

// -------- maxpool 3x3 s2 p1: 14x14 -> 7x7 --------
__global__ void k_maxpool(const float* __restrict__ x2, float* __restrict__ x) {
    int i = blockIdx.x * 256 + threadIdx.x;
    if (i >= NN * HD * 49) return;
    int p = i % 49;
    int t = i / 49;
    int py = p / 7, px = p - py * 7;
    float m = -3.4e38f;
    const float* base = x2 + (size_t)t * 196;
    #pragma unroll
    for (int ky = 0; ky < 3; ky++) {
        int y = 2 * py - 1 + ky;
        if (y < 0 || y >= 14) continue;
        #pragma unroll
        for (int kx = 0; kx < 3; kx++) {
            int xx = 2 * px - 1 + kx;
            if (xx < 0 || xx >= 14) continue;
            m = fmaxf(m, base[y * 14 + xx]);
        }
    }
    x[i] = m;
}

// -------- im2col 7x7 pad1, bf16 split --------
__global__ void k_im2col7(const float* __restrict__ x, bf* __restrict__ ch,
                          bf* __restrict__ cl) {
    int s = blockIdx.x, n = blockIdx.y;
    int sy = s / 7, sx = s - sy * 7;
    size_t ob = ((size_t)n * 49 + s) * KC;
    const float* xb = x + (size_t)n * HD * 49;
    for (int k = threadIdx.x; k < KC; k += 256) {
        int ic = k / 9, tap = k - ic * 9;
        int ky = tap / 3, kx = tap - ky * 3;
        int y = sy + ky - 1, xx = sx + kx - 1;
        float v = 0.f;
        if (y >= 0 && y < 7 && xx >= 0 && xx < 7)
            v = xb[(size_t)ic * 49 + y * 7 + xx];
        splitf(v, ch[ob + k], cl[ob + k]);
    }
}

// -------- im2col 7x7 pad1 + LayerNorm+affine+relu, bf16 split --------
__global__ void k_im2col7_ln(const float* __restrict__ virt, const float* __restrict__ mu,
                             const float* __restrict__ rstd, const float* __restrict__ gg,
                             const float* __restrict__ gb, bf* __restrict__ ch,
                             bf* __restrict__ cl) {
    int s = blockIdx.x, n = blockIdx.y;
    int sy = s / 7, sx = s - sy * 7;
    size_t ob = ((size_t)n * 49 + s) * KC;
    const float* vb = virt + (size_t)n * HD * 49;
    float m = mu[n], rs = rstd[n];
    for (int k = threadIdx.x; k < KC; k += 256) {
        int ic = k / 9, tap = k - ic * 9;
        int ky = tap / 3, kx = tap - ky * 3;
        int y = sy + ky - 1, xx = sx + kx - 1;
        float v = 0.f;
        if (y >= 0 && y < 7 && xx >= 0 && xx < 7) {
            float raw = vb[(size_t)ic * 49 + y * 7 + xx];
            v = fmaxf((raw - m) * rs * gg[ic] + gb[ic], 0.f);
        }
        splitf(v, ch[ob + k], cl[ob + k]);
    }
}

// -------- attention per (batch, spatial position) --------
__global__ __launch_bounds__(512) void k_att(const float* __restrict__ q,
                                             const float* __restrict__ kk_,
                                             const float* __restrict__ v,
                                             float* __restrict__ virt) {
    __shared__ float sq[10][512];
    __shared__ float sk[10][512];
    __shared__ float satt[10][12];
    int bp = blockIdx.x;
    int b = bp / 49, p = bp - b * 49;
    int n0 = b * R_;
    int tid = threadIdx.x;
    #pragma unroll
    for (int i = 0; i < 10; i++) {
        sq[i][tid] = q  [((size_t)(n0 + i) * HD + tid) * 49 + p];
        sk[i][tid] = kk_[((size_t)(n0 + i) * HD + tid) * 49 + p];
    }
    __syncthreads();
    int warp = tid >> 5, lane = tid & 31;
    for (int pr = warp; pr < 100; pr += 16) {
        int i = pr / 10, j = pr - i * 10;
        float s = 0.f;
        #pragma unroll
        for (int c = lane; c < 512; c += 32) s += sq[i][c] * sk[j][c];
        #pragma unroll
        for (int off = 16; off; off >>= 1) s += __shfl_xor_sync(0xffffffffu, s, off);
        if (lane == 0) satt[i][j] = s * 0.04419417382415922f;
    }
    __syncthreads();
    if (tid < 10) {
        float mx = -3.4e38f;
        #pragma unroll
        for (int j = 0; j < 10; j++) mx = fmaxf(mx, satt[tid][j]);
        float e[10], sum = 0.f;
        #pragma unroll
        for (int j = 0; j < 10; j++) { e[j] = expf(satt[tid][j] - mx); sum += e[j]; }
        float inv = 1.f / sum;
        #pragma unroll
        for (int j = 0; j < 10; j++) satt[tid][j] = e[j] * inv;
    }
    __syncthreads();
    float vv[10];
    #pragma unroll
    for (int j = 0; j < 10; j++)
        vv[j] = v[((size_t)(n0 + j) * HD + tid) * 49 + p];
    #pragma unroll
    for (int i = 0; i < 10; i++) {
        float a = 0.f;
        #pragma unroll
        for (int j = 0; j < 10; j++) a = fmaf(satt[i][j], vv[j], a);
        virt[((size_t)(n0 + i) * HD + tid) * 49 + p] = a;
    }
}

// -------- LayerNorm stats --------
__global__ void k_lnstats(const float* __restrict__ virt, float* __restrict__ mu,
                          float* __restrict__ rstd) {
    __shared__ float s1[512], s2[512];
    int n = blockIdx.x, tid = threadIdx.x;
    const float* b = virt + (size_t)n * HD * 49;
    float a = 0.f, qq = 0.f;
    for (int i = tid; i < HD * 49; i += 512) { float x = b[i]; a += x; qq += x * x; }
    s1[tid] = a; s2[tid] = qq;
    __syncthreads();
    for (int off = 256; off; off >>= 1) {
        if (tid < off) { s1[tid] += s1[tid + off]; s2[tid] += s2[tid + off]; }
        __syncthreads();
    }
    if (tid == 0) {
        float m = s1[0] * (1.f / 25088.f);
        mu[n] = m;
        rstd[n] = rsqrtf(s2[0] * (1.f / 25088.f) - m * m + 1e-5f);
    }
}

__global__ void k_homean(const float* __restrict__ x, float* __restrict__ ho) {
    int i = blockIdx.x * 256 + threadIdx.x;
    if (i >= NN * HD) return;
    const float* b = x + (size_t)i * 49;
    float s = 0.f;
    #pragma unroll
    for (int p = 0; p < 49; p++) s += b[p];
    ho[i] = s * (1.f / 49.f);
}

__global__ void k_final(const float* __restrict__ a1t, const float* __restrict__ ho,
                        const float* __restrict__ fc2, float* __restrict__ out) {
    int n = blockIdx.x, o = threadIdx.x;
    if (o >= NCLS) return;
    const float* w = fc2 + (size_t)o * 1024;
    float s = 0.f;
    for (int c = 0; c < HD; c++) s = fmaf(a1t[(size_t)c * NN + n], w[c], s);
    const float* h = ho + (size_t)n * HD;
    for (int c = 0; c < HD; c++) s = fmaf(h[c], w[512 + c], s);
    out[(size_t)n * NCLS + o] = s;
}

extern "C" void kernel_launch(void* const* d_in, const int* in_sizes, int n_in,
                              void* d_out, int out_size) {
    const float* feat_slow = (const float*)d_in[0];
    const float* feat_fast = (const float*)d_in[1];
    const float* rois      = (const float*)d_in[2];
    const float* w_reduce  = (const float*)d_in[6];
    const float* w_conv1   = (const float*)d_in[7];
    const float* w_conv2   = (const float*)d_in[8];
    const float* wq        = (const float*)d_in[9];
    const float* wk        = (const float*)d_in[10];
    const float* wv        = (const float*)d_in[11];
    const float* wm        = (const float*)d_in[12];
    const float* gn_g      = (const float*)d_in[13];
    const float* gn_b      = (const float*)d_in[14];
    const float* fc1_w     = (const float*)d_in[15];
    const float* fc2_w     = (const float*)d_in[16];
    float* out = (float*)d_out;

    float *p_tslow, *p_tfast, *p_red, *p_actor, *p_gbase, *p_av, *p_x1, *p_x2,
          *p_x, *p_qkv, *p_virt, *p_mu, *p_rstd, *p_ho, *p_a1;
    bf *p_mTh, *p_mTl, *p_ph, *p_pl, *p_gfh, *p_gfl, *p_cEh, *p_cEl, *p_cFh, *p_cFl;
    bf *p_wrh, *p_wrl, *p_wgh, *p_wgl, *p_wc2h, *p_wc2l, *p_wqh, *p_wql, *p_wmh, *p_wml;
    cudaGetSymbolAddress((void**)&p_tslow, g_tslow);
    cudaGetSymbolAddress((void**)&p_tfast, g_tfast);
    cudaGetSymbolAddress((void**)&p_mTh,   g_meanT_h);
    cudaGetSymbolAddress((void**)&p_mTl,   g_meanT_l);
    cudaGetSymbolAddress((void**)&p_ph,    g_pool_h);
    cudaGetSymbolAddress((void**)&p_pl,    g_pool_l);
    cudaGetSymbolAddress((void**)&p_red,   g_red);
    cudaGetSymbolAddress((void**)&p_actor, g_actor);
    cudaGetSymbolAddress((void**)&p_gfh,   g_gf_h);
    cudaGetSymbolAddress((void**)&p_gfl,   g_gf_l);
    cudaGetSymbolAddress((void**)&p_gbase, g_gbase);
    cudaGetSymbolAddress((void**)&p_av,    g_av);
    cudaGetSymbolAddress((void**)&p_x1,    g_x1);
    cudaGetSymbolAddress((void**)&p_cEh,   g_colE_h);
    cudaGetSymbolAddress((void**)&p_cEl,   g_colE_l);
    cudaGetSymbolAddress((void**)&p_x2,    g_x2);
    cudaGetSymbolAddress((void**)&p_x,     g_x);
    cudaGetSymbolAddress((void**)&p_cFh,   g_colF_h);
    cudaGetSymbolAddress((void**)&p_cFl,   g_colF_l);
    cudaGetSymbolAddress((void**)&p_qkv,   g_qkv);
    cudaGetSymbolAddress((void**)&p_virt,  g_virt);
    cudaGetSymbolAddress((void**)&p_mu,    g_mu);
    cudaGetSymbolAddress((void**)&p_rstd,  g_rstd);
    cudaGetSymbolAddress((void**)&p_ho,    g_ho);
    cudaGetSymbolAddress((void**)&p_a1,    g_a1);
    cudaGetSymbolAddress((void**)&p_wrh,   g_wred_h);
    cudaGetSymbolAddress((void**)&p_wrl,   g_wred_l);
    cudaGetSymbolAddress((void**)&p_wgh,   g_wg_h);
    cudaGetSymbolAddress((void**)&p_wgl,   g_wg_l);
    cudaGetSymbolAddress((void**)&p_wc2h,  g_wc2_h);
    cudaGetSymbolAddress((void**)&p_wc2l,  g_wc2_l);
    cudaGetSymbolAddress((void**)&p_wqh,   g_wqkv_h);
    cudaGetSymbolAddress((void**)&p_wql,   g_wqkv_l);
    cudaGetSymbolAddress((void**)&p_wmh,   g_wm2_h);
    cudaGetSymbolAddress((void**)&p_wml,   g_wm2_l);

    // ---- weight splits ----
    {
        long t;
        t = (long)RD * CC;
        k_splits<<<(int)((t + 255) / 256), 256>>>(w_reduce, CC, 0, CC, t, p_wrh, p_wrl);
        t = (long)HD * RD;
        k_splits<<<(int)((t + 255) / 256), 256>>>(w_conv1, 2 * RD, 0, RD, t, p_wgh, p_wgl);
        t = (long)HD * KC;
        k_splits<<<(int)((t + 255) / 256), 256>>>(w_conv2, KC, 0, KC, t, p_wc2h, p_wc2l);
        const float* srcs[3] = {wq, wk, wv};
        for (int d = 0; d < 2; d++) {
            for (int wch = 0; wch < 3; wch++) {
                size_t doff = ((size_t)d * 3 + wch) * HD * KC;
                k_splits<<<(int)((t + 255) / 256), 256>>>(srcs[wch] + (size_t)d * HD * KC,
                                                          KC, 0, KC, t,
                                                          p_wqh + doff, p_wql + doff);
            }
            k_splits<<<(int)((t + 255) / 256), 256>>>(wm + (size_t)d * HD * KC, KC, 0, KC, t,
                                                      p_wmh + (size_t)d * HD * KC,
                                                      p_wml + (size_t)d * HD * KC);
        }
    }

    // ---- features ----
    k_transpose<<<dim3(CS / 32, 8, B_ * NS), dim3(32, 8)>>>(feat_slow, p_tslow, CS, NS);
    k_transpose<<<dim3(CF / 32, 8, B_ * NF), dim3(32, 8)>>>(feat_fast, p_tfast, CF, NF);
    k_meansplit<<<dim3(CC / 32, 8, B_), dim3(32, 8)>>>(feat_slow, feat_fast, p_mTh, p_mTl);
    k_roipool<<<dim3(49, NN), 256>>>(rois, p_tslow, p_tfast, p_ph, p_pl);

    // ---- reduce conv on pooled rois + rowmax ----
    k_tgemm<0><<<dim3(31, 8), 256>>>(p_wrh, p_wrl, p_ph, p_pl, 3920, CC,
                                     p_red, nullptr, nullptr);
    k_rowmax<<<(NN * RD + 255) / 256, 256>>>(p_red, p_actor);

    // ---- gfeat ----
    k_tgemm<4><<<dim3(16, 8), 256>>>(p_wrh, p_wrl, p_mTh, p_mTl, 2048, CC,
                                     nullptr, p_gfh, p_gfl);
    // ---- gbase ----
    k_tgemm<5><<<dim3(16, 4), 256>>>(p_wgh, p_wgl, p_gfh, p_gfl, 2048, RD,
                                     p_gbase, nullptr, nullptr);
    // ---- av ----
    k_gemm<80, 0><<<dim3(2, 4), 256>>>(w_conv1, 2 * RD, RD, p_actor, p_av, RD);
    // ---- x1 ----
    k_x1<<<(NN * HD * HW + 255) / 256, 256>>>(p_gbase, p_av, p_x1);
    // ---- conv2 ----
    k_im2col16<<<dim3(196, NN), 256>>>(p_x1, p_cEh, p_cEl);
    k_tgemm<2><<<dim3(123, 4), 256>>>(p_wc2h, p_wc2l, p_cEh, p_cEl, 15680, KC,
                                      p_x2, nullptr, nullptr);
    // ---- maxpool ----
    k_maxpool<<<(NN * HD * 49 + 255) / 256, 256>>>(p_x2, p_x);

    // ---- HR2O blocks ----
    for (int d = 0; d < 2; d++) {
        k_im2col7<<<dim3(49, NN), 256>>>(p_x, p_cFh, p_cFl);
        k_tgemm<1><<<dim3(31, 12), 256>>>(p_wqh + (size_t)d * 3 * HD * KC,
                                          p_wql + (size_t)d * 3 * HD * KC,
                                          p_cFh, p_cFl, 3920, KC,
                                          p_qkv, nullptr, nullptr);
        k_att<<<B_ * 49, 512>>>(p_qkv, p_qkv + (size_t)NN * HD * 49,
                                p_qkv + (size_t)2 * NN * HD * 49, p_virt);
        k_lnstats<<<NN, 512>>>(p_virt, p_mu, p_rstd);
        k_im2col7_ln<<<dim3(49, NN), 256>>>(p_virt, p_mu, p_rstd,
                                            gn_g + (size_t)d * HD, gn_b + (size_t)d * HD,
                                            p_cFh, p_cFl);
        k_tgemm<3><<<dim3(31, 4), 256>>>(p_wmh + (size_t)d * HD * KC,
                                         p_wml + (size_t)d * HD * KC,
                                         p_cFh, p_cFl, 3920, KC,
                                         p_x, nullptr, nullptr);
    }

    // ---- head ----
    k_homean<<<(NN * HD + 255) / 256, 256>>>(p_x, p_ho);
    k_gemm<80, 1><<<dim3(2, 4), 256>>>(fc1_w, RD, 0, p_actor, p_a1, RD);
    k_final<<<NN, 64>>>(p_a1, p_ho, fc2_w, out);
}

// round 7
// speedup vs baseline: 2.7811x; 1.0183x over previous
#include <cuda_runtime.h>
#include <cuda_bf16.h>
#include <stdint.h>
#include <math.h>

#define B_   8
#define R_   10
#define NN   80
#define CS   2048
#define CF   256
#define NS   8
#define NF   32
#define HH   16
#define WW   16
#define HW   256
#define CC   2304
#define RD   1024
#define HD   512
#define NCLS 60
#define KC   4608

typedef __nv_bfloat16 bf;

// ---------------- scratch ----------------
__device__ __align__(128) float g_tslow[(size_t)B_*NS*HW*CS];
__device__ __align__(128) float g_tfast[(size_t)B_*NF*HW*CF];
__device__ __align__(128) bf    g_meanT_h[(size_t)B_*HW*CC];
__device__ __align__(128) bf    g_meanT_l[(size_t)B_*HW*CC];
__device__ __align__(128) bf    g_pool_h[(size_t)NN*49*CC];
__device__ __align__(128) bf    g_pool_l[(size_t)NN*49*CC];
__device__ __align__(128) float g_red  [(size_t)RD*3920];
__device__ __align__(128) float g_actor[(size_t)NN*RD];
__device__ __align__(128) bf    g_gf_h [(size_t)B_*HW*RD];
__device__ __align__(128) bf    g_gf_l [(size_t)B_*HW*RD];
__device__ __align__(128) float g_gbase[(size_t)B_*HD*HW];
__device__ __align__(128) float g_av   [(size_t)HD*NN];
__device__ __align__(128) float g_x1   [(size_t)NN*HD*HW];
__device__ __align__(128) bf    g_colE_h[(size_t)NN*196*KC];
__device__ __align__(128) bf    g_colE_l[(size_t)NN*196*KC];
__device__ __align__(128) float g_x2   [(size_t)NN*HD*196];
__device__ __align__(128) float g_x    [(size_t)NN*HD*49];
__device__ __align__(128) bf    g_colF_h[(size_t)NN*49*KC];
__device__ __align__(128) bf    g_colF_l[(size_t)NN*49*KC];
__device__ __align__(128) float g_qkv  [(size_t)3*NN*HD*49];
__device__ __align__(128) float g_virt [(size_t)NN*HD*49];
__device__ __align__(128) float g_mu   [NN];
__device__ __align__(128) float g_rstd [NN];
__device__ __align__(128) float g_ho   [(size_t)NN*HD];
__device__ __align__(128) float g_a1   [(size_t)HD*NN];
// split weights
__device__ __align__(128) bf g_wred_h[(size_t)RD*CC];
__device__ __align__(128) bf g_wred_l[(size_t)RD*CC];
__device__ __align__(128) bf g_wg_h  [(size_t)HD*RD];
__device__ __align__(128) bf g_wg_l  [(size_t)HD*RD];
__device__ __align__(128) bf g_wc2_h [(size_t)HD*KC];
__device__ __align__(128) bf g_wc2_l [(size_t)HD*KC];
__device__ __align__(128) bf g_wqkv_h[(size_t)2*3*HD*KC];
__device__ __align__(128) bf g_wqkv_l[(size_t)2*3*HD*KC];
__device__ __align__(128) bf g_wm2_h [(size_t)2*HD*KC];
__device__ __align__(128) bf g_wm2_l [(size_t)2*HD*KC];

__device__ __forceinline__ void splitf(float x, bf& h, bf& l) {
    h = __float2bfloat16(x);
    l = __float2bfloat16(x - __bfloat162float(h));
}

// -------- weight split (strided) --------
__global__ void k_splits(const float* __restrict__ src, int ld, int koff, int K,
                         long total, bf* __restrict__ h, bf* __restrict__ l) {
    long i = (long)blockIdx.x * 256 + threadIdx.x;
    if (i >= total) return;
    long r = i / K; int c = (int)(i - r * K);
    float x = src[r * ld + koff + c];
    splitf(x, h[i], l[i]);
}

// -------- transpose [b][C][T][p] -> [b][t][p][C] --------
__global__ void k_transpose(const float* __restrict__ src, float* __restrict__ dst,
                            int C, int T) {
    __shared__ float tile[32][33];
    int bt = blockIdx.z;
    int b = bt / T, t = bt - b * T;
    int c0 = blockIdx.x << 5, p0 = blockIdx.y << 5;
    int x = threadIdx.x;
    #pragma unroll
    for (int r = 0; r < 4; r++) {
        int yy = threadIdx.y + r * 8;
        tile[yy][x] = src[((size_t)(b * C + c0 + yy) * T + t) * HW + p0 + x];
    }
    __syncthreads();
    #pragma unroll
    for (int r = 0; r < 4; r++) {
        int yy = threadIdx.y + r * 8;
        dst[((size_t)(b * T + t) * HW + p0 + yy) * C + c0 + x] = tile[x][yy];
    }
}

// -------- temporal means -> channel-last bf16 split [b][p][CC] --------
__global__ void k_meansplit(const float* __restrict__ slow, const float* __restrict__ fast,
                            bf* __restrict__ mh, bf* __restrict__ ml) {
    __shared__ float tile[32][33];
    int b = blockIdx.z;
    int c0 = blockIdx.x << 5, p0 = blockIdx.y << 5;
    int x = threadIdx.x;
    #pragma unroll
    for (int r = 0; r < 4; r++) {
        int cy = threadIdx.y + r * 8;
        int c = c0 + cy;
        float s = 0.f;
        if (c < CS) {
            const float* base = slow + ((size_t)(b * CS + c) * NS) * HW + p0 + x;
            #pragma unroll
            for (int t = 0; t < NS; t++) s += base[t * HW];
            s *= (1.f / NS);
        } else {
            const float* base = fast + ((size_t)(b * CF + (c - CS)) * NF) * HW + p0 + x;
            #pragma unroll
            for (int t = 0; t < NF; t++) s += base[t * HW];
            s *= (1.f / NF);
        }
        tile[cy][x] = s;
    }
    __syncthreads();
    #pragma unroll
    for (int r = 0; r < 4; r++) {
        int py = threadIdx.y + r * 8;
        size_t o = (size_t)(b * 256 + p0 + py) * CC + c0 + x;
        splitf(tile[x][py], mh[o], ml[o]);
    }
}

// -------- roi-align: build compact sample lists in smem, then gather --------
__device__ __forceinline__ bool make_entry(const float* __restrict__ r5,
                                           int py, int px, int iy, int ix,
                                           int T, int t, float4& w, int4& o) {
    if (r5[1] == 1.f && r5[2] == 1.f && r5[3] == 1.f && r5[4] == 1.f) return false;
    float rx1 = r5[1] * WW, ry1 = r5[2] * HH, rx2 = r5[3] * WW, ry2 = r5[4] * HH;
    float roi_w = fmaxf(rx2 - rx1, 1.f), roi_h = fmaxf(ry2 - ry1, 1.f);
    float bw = roi_w * (1.f / 7.f), bh = roi_h * (1.f / 7.f);
    float gw = ceilf(bw), gh = ceilf(bh);
    if ((float)iy >= gh || (float)ix >= gw) return false;
    float yy = ry1 + py * bh + (iy + 0.5f) * bh / gh;
    float xx = rx1 + px * bw + (ix + 0.5f) * bw / gw;
    if (!(yy > -1.f && yy < (float)HH && xx > -1.f && xx < (float)WW)) return false;
    float minv = 1.f / (gh * gw);
    float y = fminf(fmaxf(yy, 0.f), HH - 1.f);
    float x = fminf(fmaxf(xx, 0.f), WW - 1.f);
    int y0 = (int)floorf(y), x0 = (int)floorf(x);
    int y1i = min(y0 + 1, HH - 1), x1i = min(x0 + 1, WW - 1);
    float ly = y - (float)y0, lx = x - (float)x0;
    float hy = 1.f - ly, hx = 1.f - lx;
    w = make_float4(hy * hx * minv, hy * lx * minv, ly * hx * minv, ly * lx * minv);
    int bi = (int)r5[0];
    int base = (bi * T + t) * HW;
    o = make_int4(base + y0 * WW + x0, base + y0 * WW + x1i,
                  base + y1i * WW + x0, base + y1i * WW + x1i);
    return true;
}

__global__ __launch_bounds__(256) void k_roipool(
        const float* __restrict__ rois, const float* __restrict__ tslow,
        const float* __restrict__ tfast, bf* __restrict__ ph, bf* __restrict__ pl) {
    __shared__ float4 swS[72];  __shared__ int4 soS[72];
    __shared__ float4 swF[288]; __shared__ int4 soF[288];
    __shared__ int cS, cF, fS, fF;
    int s = blockIdx.x, n = blockIdx.y;
    int py = s / 7, px = s - py * 7;
    int tid = threadIdx.x;
    if (tid == 0) { cS = 0; cF = 0; fS = 0; fF = 0; }
    __syncthreads();

    // frame-valid counts
    if (tid < NS) {
        const float* r5 = rois + ((size_t)n * NF + (4 * tid + 3)) * 5;
        if (!(r5[1] == 1.f && r5[2] == 1.f && r5[3] == 1.f && r5[4] == 1.f))
            atomicAdd(&fS, 1);
    } else if (tid >= 32 && tid < 32 + NF) {
        const float* r5 = rois + ((size_t)n * NF + (tid - 32)) * 5;
        if (!(r5[1] == 1.f && r5[2] == 1.f && r5[3] == 1.f && r5[4] == 1.f))
            atomicAdd(&fF, 1);
    }
    // slow entries (8 frames x 9 samples)
    for (int i = tid; i < NS * 9; i += 256) {
        int t = i / 9, rem = i - t * 9;
        int iy = rem / 3, ix = rem - iy * 3;
        const float* r5 = rois + ((size_t)n * NF + (4 * t + 3)) * 5;
        float4 w; int4 o;
        if (make_entry(r5, py, px, iy, ix, NS, t, w, o)) {
            int slot = atomicAdd(&cS, 1);
            swS[slot] = w; soS[slot] = o;
        }
    }
    // fast entries (32 frames x 9 samples)
    for (int i = tid; i < NF * 9; i += 256) {
        int t = i / 9, rem = i - t * 9;
        int iy = rem / 3, ix = rem - iy * 3;
        const float* r5 = rois + ((size_t)n * NF + t) * 5;
        float4 w; int4 o;
        if (make_entry(r5, py, px, iy, ix, NF, t, w, o)) {
            int slot = atomicAdd(&cF, 1);
            swF[slot] = w; soF[slot] = o;
        }
    }
    __syncthreads();

    size_t ob = ((size_t)n * 49 + s) * CC;

    // slow gather: 8 contiguous channels per thread via 2x float4
    {
        float acc[8];
        #pragma unroll
        for (int j = 0; j < 8; j++) acc[j] = 0.f;
        int c0 = tid * 8;
        int nE = cS;
        for (int e = 0; e < nE; e++) {
            float4 w = swS[e]; int4 o = soS[e];
            const float* b00 = tslow + (size_t)o.x * CS + c0;
            const float* b01 = tslow + (size_t)o.y * CS + c0;
            const float* b10 = tslow + (size_t)o.z * CS + c0;
            const float* b11 = tslow + (size_t)o.w * CS + c0;
            #pragma unroll
            for (int h = 0; h < 2; h++) {
                float4 f00 = *(const float4*)(b00 + h * 4);
                float4 f01 = *(const float4*)(b01 + h * 4);
                float4 f10 = *(const float4*)(b10 + h * 4);
                float4 f11 = *(const float4*)(b11 + h * 4);
                acc[h*4+0] += w.x*f00.x + w.y*f01.x + w.z*f10.x + w.w*f11.x;
                acc[h*4+1] += w.x*f00.y + w.y*f01.y + w.z*f10.y + w.w*f11.y;
                acc[h*4+2] += w.x*f00.z + w.y*f01.z + w.z*f10.z + w.w*f11.z;
                acc[h*4+3] += w.x*f00.w + w.y*f01.w + w.z*f10.w + w.w*f11.w;
            }
        }
        float sc = 1.f / (float)max(fS, 1);
        #pragma unroll
        for (int j = 0; j < 8; j++) {
            size_t o = ob + c0 + j;
            splitf(acc[j] * sc, ph[o], pl[o]);
        }
    }
    // fast gather: 1 channel per thread
    {
        float af = 0.f;
        int c = tid;
        int nE = cF;
        for (int e = 0; e < nE; e++) {
            float4 w = swF[e]; int4 o = soF[e];
            af += w.x * tfast[(size_t)o.x * CF + c] + w.y * tfast[(size_t)o.y * CF + c]
                + w.z * tfast[(size_t)o.z * CF + c] + w.w * tfast[(size_t)o.w * CF + c];
        }
        size_t o = ob + CS + c;
        splitf(af / (float)max(fF, 1), ph[o], pl[o]);
    }
}

// ================= tensor-core GEMM (bf16 3-term split, mma.sync m16n8k16) ======
// SMEM row stride padded 8->12 words: fragment-load banks (12g+tg)%32 are all
// distinct -> conflict-free; cp.async 16B alignment preserved (48*row+16*chunk).
#define SPAD 12
__device__ __forceinline__ uint32_t s2u(const void* p) {
    return (uint32_t)__cvta_generic_to_shared(p);
}
__device__ __forceinline__ void cpa16(uint32_t s, const void* g, bool pred) {
    asm volatile("cp.async.cg.shared.global [%0], [%1], 16, %2;\n"
                 :: "r"(s), "l"(g), "r"(pred ? 16 : 0));
}
__device__ __forceinline__ void mma16816(float* c, const uint32_t* a, const uint32_t* b) {
    asm volatile(
        "mma.sync.aligned.m16n8k16.row.col.f32.bf16.bf16.f32 "
        "{%0,%1,%2,%3},{%4,%5,%6,%7},{%8,%9},{%0,%1,%2,%3};\n"
        : "+f"(c[0]), "+f"(c[1]), "+f"(c[2]), "+f"(c[3])
        : "r"(a[0]), "r"(a[1]), "r"(a[2]), "r"(a[3]), "r"(b[0]), "r"(b[1]));
}

// MODE 0: dst[m*N+col]
// MODE 1: qkv  -> dst[((m>>9)*NN + col/49)*HD*49 + (m&511)*49 + col%49]
// MODE 2: relu -> x2[(col/196*HD + m)*196 + col%196]
// MODE 3: acc  -> x [(col/49 *HD + m)*49  + col%49]
// MODE 4: bf16 split -> dsth/dstl[col*RD + m]
// MODE 5: gbase[((col>>8)*HD + m)*256 + (col&255)]
template<int MODE>
__global__ __launch_bounds__(256, 1) void k_tgemm(
    const bf* __restrict__ Ah, const bf* __restrict__ Al,
    const bf* __restrict__ Bh, const bf* __restrict__ Bl,
    int Ndim, int K,
    float* __restrict__ dst, bf* __restrict__ dsth, bf* __restrict__ dstl) {
    __shared__ uint32_t sAH[2][128*SPAD], sAL[2][128*SPAD];
    __shared__ uint32_t sBH[2][128*SPAD], sBL[2][128*SPAD];
    int tid = threadIdx.x;
    int bm0 = blockIdx.y << 7, bn0 = blockIdx.x << 7;
    int wid = tid >> 5, lane = tid & 31;
    int wm = wid >> 2, wn = wid & 3;
    int g = lane >> 2, tg = lane & 3;

    int lrow = tid >> 1, lchk = tid & 1;
    const bf* gAh = Ah + (size_t)(bm0 + lrow) * K + lchk * 8;
    const bf* gAl = Al + (size_t)(bm0 + lrow) * K + lchk * 8;
    bool bpred = (bn0 + lrow) < Ndim;
    long brow = bpred ? (bn0 + lrow) : (Ndim - 1);
    const bf* gBh = Bh + (size_t)brow * K + lchk * 8;
    const bf* gBl = Bl + (size_t)brow * K + lchk * 8;
    int soff = lrow * SPAD + lchk * 4;

    float acc[4][4][4];
    #pragma unroll
    for (int i = 0; i < 4; i++)
        #pragma unroll
        for (int j = 0; j < 4; j++)
            #pragma unroll
            for (int r = 0; r < 4; r++) acc[i][j][r] = 0.f;

    int KT = K >> 4;
    cpa16(s2u(&sAH[0][soff]), gAh, true);
    cpa16(s2u(&sAL[0][soff]), gAl, true);
    cpa16(s2u(&sBH[0][soff]), gBh, bpred);
    cpa16(s2u(&sBL[0][soff]), gBl, bpred);
    asm volatile("cp.async.commit_group;\n");

    for (int kt = 0; kt < KT; kt++) {
        asm volatile("cp.async.wait_group 0;\n");
        __syncthreads();
        if (kt + 1 < KT) {
            int st = (kt + 1) & 1;
            size_t off = (size_t)(kt + 1) << 4;
            cpa16(s2u(&sAH[st][soff]), gAh + off, true);
            cpa16(s2u(&sAL[st][soff]), gAl + off, true);
            cpa16(s2u(&sBH[st][soff]), gBh + off, bpred);
            cpa16(s2u(&sBL[st][soff]), gBl + off, bpred);
            asm volatile("cp.async.commit_group;\n");
        }
        int st = kt & 1;
        const uint32_t* pAH = sAH[st];
        const uint32_t* pAL = sAL[st];
        const uint32_t* pBH = sBH[st];
        const uint32_t* pBL = sBL[st];
        uint32_t ah[4][4], al[4][4], bh[4][2], bl[4][2];
        #pragma unroll
        for (int mi = 0; mi < 4; mi++) {
            int r0 = wm * 64 + mi * 16 + g;
            ah[mi][0] = pAH[r0 * SPAD + tg];
            ah[mi][1] = pAH[(r0 + 8) * SPAD + tg];
            ah[mi][2] = pAH[r0 * SPAD + tg + 4];
            ah[mi][3] = pAH[(r0 + 8) * SPAD + tg + 4];
            al[mi][0] = pAL[r0 * SPAD + tg];
            al[mi][1] = pAL[(r0 + 8) * SPAD + tg];
            al[mi][2] = pAL[r0 * SPAD + tg + 4];
            al[mi][3] = pAL[(r0 + 8) * SPAD + tg + 4];
        }
        #pragma unroll
        for (int nj = 0; nj < 4; nj++) {
            int c0 = wn * 32 + nj * 8 + g;
            bh[nj][0] = pBH[c0 * SPAD + tg];
            bh[nj][1] = pBH[c0 * SPAD + tg + 4];
            bl[nj][0] = pBL[c0 * SPAD + tg];
            bl[nj][1] = pBL[c0 * SPAD + tg + 4];
        }
        #pragma unroll
        for (int mi = 0; mi < 4; mi++)
            #pragma unroll
            for (int nj = 0; nj < 4; nj++) {
                mma16816(acc[mi][nj], ah[mi], bh[nj]);
                mma16816(acc[mi][nj], ah[mi], bl[nj]);
                mma16816(acc[mi][nj], al[mi], bh[nj]);
            }
        // no trailing sync: next iteration's top sync orders compute(kt)
        // before any prefetch that overwrites stage kt&1.
    }

    #pragma unroll
    for (int mi = 0; mi < 4; mi++) {
        int rbase = bm0 + wm * 64 + mi * 16 + g;
        #pragma unroll
        for (int nj = 0; nj < 4; nj++) {
            int cbase = bn0 + wn * 32 + nj * 8 + tg * 2;
            #pragma unroll
            for (int ri = 0; ri < 4; ri++) {
                int row = rbase + ((ri >> 1) << 3);
                int col = cbase + (ri & 1);
                if (col >= Ndim) continue;
                float v = acc[mi][nj][ri];
                if (MODE == 0) {
                    dst[(size_t)row * Ndim + col] = v;
                } else if (MODE == 1) {
                    int which = row >> 9, c = row & 511;
                    int n = col / 49, s = col - n * 49;
                    dst[(((size_t)which * NN + n) * HD + c) * 49 + s] = v;
                } else if (MODE == 2) {
                    int n = col / 196, s = col - n * 196;
                    dst[((size_t)n * HD + row) * 196 + s] = fmaxf(v, 0.f);
                } else if (MODE == 3) {
                    int n = col / 49, s = col - n * 49;
                    size_t o = ((size_t)n * HD + row) * 49 + s;
                    dst[o] += v;
                } else if (MODE == 4) {
                    size_t o = (size_t)col * RD + row;
                    splitf(v, dsth[o], dstl[o]);
                } else if (MODE == 5) {
                    int b = col >> 8, p = col & 255;
                    dst[((size_t)b * HD + row) * 256 + p] = v;
                }
            }
        }
    }
}

// -------- actor = rowmax over 49 bins of g_red --------
__global__ void k_rowmax(const float* __restrict__ red, float* __restrict__ actor) {
    int i = blockIdx.x * 256 + threadIdx.x;
    if (i >= NN * RD) return;
    int m = i % RD, n = i / RD;
    const float* b = red + (size_t)m * 3920 + n * 49;
    float mx = -3.4e38f;
    #pragma unroll
    for (int s = 0; s < 49; s++) mx = fmaxf(mx, b[s]);
    actor[(size_t)n * RD + m] = mx;
}

// -------- small scalar GEMM (av / fc1) --------
template<int S, int EPI>
__global__ __launch_bounds__(256) void k_gemm(
    const float* __restrict__ A, int lda, int aoff,
    const float* __restrict__ Bm,
    float* __restrict__ C, int K) {
    __shared__ float As[16][132];
    __shared__ float Bs[16][68];
    int s0 = blockIdx.x << 6;
    int m0 = blockIdx.y << 7;
    int tid = threadIdx.x;
    int tx = tid & 15, ty = tid >> 4;
    int lm = tid >> 2;
    int lk = (tid & 3) << 2;
    const float* Arow0 = A + (size_t)(m0 + lm) * lda + aoff + lk;
    const float* Arow1 = Arow0 + (size_t)64 * lda;
    float acc[8][4];
    #pragma unroll
    for (int i = 0; i < 8; i++)
        #pragma unroll
        for (int j = 0; j < 4; j++) acc[i][j] = 0.f;
    for (int k0 = 0; k0 < K; k0 += 16) {
        float4 a0 = *(const float4*)(Arow0 + k0);
        float4 a1 = *(const float4*)(Arow1 + k0);
        As[lk + 0][lm] = a0.x; As[lk + 1][lm] = a0.y;
        As[lk + 2][lm] = a0.z; As[lk + 3][lm] = a0.w;
        As[lk + 0][lm + 64] = a1.x; As[lk + 1][lm + 64] = a1.y;
        As[lk + 2][lm + 64] = a1.z; As[lk + 3][lm + 64] = a1.w;
        int s = s0 + lm;
        float4 bv = make_float4(0.f, 0.f, 0.f, 0.f);
        if (s < S) bv = *(const float4*)(Bm + (size_t)s * K + k0 + lk);
        Bs[lk + 0][lm] = bv.x; Bs[lk + 1][lm] = bv.y;
        Bs[lk + 2][lm] = bv.z; Bs[lk + 3][lm] = bv.w;
        __syncthreads();
        #pragma unroll
        for (int kk = 0; kk < 16; kk++) {
            float a[8], b[4];
            #pragma unroll
            for (int i = 0; i < 8; i++) a[i] = As[kk][ty + (i << 4)];
            #pragma unroll
            for (int j = 0; j < 4; j++) b[j] = Bs[kk][tx + (j << 4)];
            #pragma unroll
            for (int i = 0; i < 8; i++)
                #pragma unroll
                for (int j = 0; j < 4; j++)
                    acc[i][j] = fmaf(a[i], b[j], acc[i][j]);
        }
        __syncthreads();
    }
    #pragma unroll
    for (int i = 0; i < 8; i++) {
        int m = m0 + ty + (i << 4);
        #pragma unroll
        for (int j = 0; j < 4; j++) {
            int sg = s0 + tx + (j << 4);
            if (sg < S) {
                float vv = acc[i][j];
                if (EPI == 1) vv = fmaxf(vv, 0.f);
                C[(size_t)m * S + sg] = vv;
            }
        }
    }
}

// -------- x1 = relu(gbase[b] + av) --------
__global__ void k_x1(const float* __restrict__ gbase, const float* __restrict__ av,
                     float* __restrict__ x1) {
    int i = blockIdx.x * 256 + threadIdx.x;
    if (i >= NN * HD * HW) return;
    int p = i & 255;
    int t = i >> 8;
    int c = t % HD;
    int n = t / HD;
    int b = n / R_;
    float v = gbase[((size_t)(b * HD + c)) * HW + p] + av[(size_t)c * NN + n];
    x1[i] = fmaxf(v, 0.f);
}

// -------- im2col 16x16 -> 14x14, bf16 split --------
__global__ void k_im2col16(const float* __restrict__ x1, bf* __restrict__ ch,
                           bf* __restrict__ cl) {
    int s = blockIdx.x, n = blockIdx.y;
    int sy = s / 14, sx = s - sy * 14;
    size_t ob = ((size_t)n * 196 + s) * KC;
    const float* xb = x1 + (size_t)n * HD * HW;
    for (int k = threadIdx.x; k < KC; k += 256) {
        int ic = k / 9, tap = k - ic * 9;
        int ky = tap / 3, kx = tap - ky * 3;
        splitf(xb[(size_t)ic * HW + (sy + ky) * 16 + sx + kx], ch[ob + k], cl[ob + k]);
    }
}

// -------- maxpool 3x3 s2 p1: 14x14 -> 7x7 --------
__global__ void k_maxpool(const float* __restrict__ x2, float* __restrict__ x) {
    int i = blockIdx.x * 256 + threadIdx.x;
    if (i >= NN * HD * 49) return;
    int p = i % 49;
    int t = i / 49;
    int py = p / 7, px = p - py * 7;
    float m = -3.4e38f;
    const float* base = x2 + (size_t)t * 196;
    #pragma unroll
    for (int ky = 0; ky < 3; ky++) {
        int y = 2 * py - 1 + ky;
        if (y < 0 || y >= 14) continue;
        #pragma unroll
        for (int kx = 0; kx < 3; kx++) {
            int xx = 2 * px - 1 + kx;
            if (xx < 0 || xx >= 14) continue;
            m = fmaxf(m, base[y * 14 + xx]);
        }
    }
    x[i] = m;
}

// -------- im2col 7x7 pad1, bf16 split --------
__global__ void k_im2col7(const float* __restrict__ x, bf* __restrict__ ch,
                          bf* __restrict__ cl) {
    int s = blockIdx.x, n = blockIdx.y;
    int sy = s / 7, sx = s - sy * 7;
    size_t ob = ((size_t)n * 49 + s) * KC;
    const float* xb = x + (size_t)n * HD * 49;
    for (int k = threadIdx.x; k < KC; k += 256) {
        int ic = k / 9, tap = k - ic * 9;
        int ky = tap / 3, kx = tap - ky * 3;
        int y = sy + ky - 1, xx = sx + kx - 1;
        float v = 0.f;
        if (y >= 0 && y < 7 && xx >= 0 && xx < 7)
            v = xb[(size_t)ic * 49 + y * 7 + xx];
        splitf(v, ch[ob + k], cl[ob + k]);
    }
}

// -------- im2col 7x7 pad1 + LayerNorm+affine+relu, bf16 split --------
__global__ void k_im2col7_ln(const float* __restrict__ virt, const float* __restrict__ mu,
                             const float* __restrict__ rstd, const float* __restrict__ gg,
                             const float* __restrict__ gb, bf* __restrict__ ch,
                             bf* __restrict__ cl) {
    int s = blockIdx.x, n = blockIdx.y;
    int sy = s / 7, sx = s - sy * 7;
    size_t ob = ((size_t)n * 49 + s) * KC;
    const float* vb = virt + (size_t)n * HD * 49;
    float m = mu[n], rs = rstd[n];
    for (int k = threadIdx.x; k < KC; k += 256) {
        int ic = k / 9, tap = k - ic * 9;
        int ky = tap / 3, kx = tap - ky * 3;
        int y = sy + ky - 1, xx = sx + kx - 1;
        float v = 0.f;
        if (y >= 0 && y < 7 && xx >= 0 && xx < 7) {
            float raw = vb[(size_t)ic * 49 + y * 7 + xx];
            v = fmaxf((raw - m) * rs * gg[ic] + gb[ic], 0.f);
        }
        splitf(v, ch[ob + k], cl[ob + k]);
    }
}

// -------- attention per (batch, spatial position) --------
__global__ __launch_bounds__(512) void k_att(const float* __restrict__ q,
                                             const float* __restrict__ kk_,
                                             const float* __restrict__ v,
                                             float* __restrict__ virt) {
    __shared__ float sq[10][512];
    __shared__ float sk[10][512];
    __shared__ float satt[10][12];
    int bp = blockIdx.x;
    int b = bp / 49, p = bp - b * 49;
    int n0 = b * R_;
    int tid = threadIdx.x;
    #pragma unroll
    for (int i = 0; i < 10; i++) {
        sq[i][tid] = q  [((size_t)(n0 + i) * HD + tid) * 49 + p];
        sk[i][tid] = kk_[((size_t)(n0 + i) * HD + tid) * 49 + p];
    }
    __syncthreads();
    int warp = tid >> 5, lane = tid & 31;
    for (int pr = warp; pr < 100; pr += 16) {
        int i = pr / 10, j = pr - i * 10;
        float s = 0.f;
        #pragma unroll
        for (int c = lane; c < 512; c += 32) s += sq[i][c] * sk[j][c];
        #pragma unroll
        for (int off = 16; off; off >>= 1) s += __shfl_xor_sync(0xffffffffu, s, off);
        if (lane == 0) satt[i][j] = s * 0.04419417382415922f;
    }
    __syncthreads();
    if (tid < 10) {
        float mx = -3.4e38f;
        #pragma unroll
        for (int j = 0; j < 10; j++) mx = fmaxf(mx, satt[tid][j]);
        float e[10], sum = 0.f;
        #pragma unroll
        for (int j = 0; j < 10; j++) { e[j] = expf(satt[tid][j] - mx); sum += e[j]; }
        float inv = 1.f / sum;
        #pragma unroll
        for (int j = 0; j < 10; j++) satt[tid][j] = e[j] * inv;
    }
    __syncthreads();
    float vv[10];
    #pragma unroll
    for (int j = 0; j < 10; j++)
        vv[j] = v[((size_t)(n0 + j) * HD + tid) * 49 + p];
    #pragma unroll
    for (int i = 0; i < 10; i++) {
        float a = 0.f;
        #pragma unroll
        for (int j = 0; j < 10; j++) a = fmaf(satt[i][j], vv[j], a);
        virt[((size_t)(n0 + i) * HD + tid) * 49 + p] = a;
    }
}

// -------- LayerNorm stats --------
__global__ void k_lnstats(const float* __restrict__ virt, float* __restrict__ mu,
                          float* __restrict__ rstd) {
    __shared__ float s1[512], s2[512];
    int n = blockIdx.x, tid = threadIdx.x;
    const float* b = virt + (size_t)n * HD * 49;
    float a = 0.f, qq = 0.f;
    for (int i = tid; i < HD * 49; i += 512) { float x = b[i]; a += x; qq += x * x; }
    s1[tid] = a; s2[tid] = qq;
    __syncthreads();
    for (int off = 256; off; off >>= 1) {
        if (tid < off) { s1[tid] += s1[tid + off]; s2[tid] += s2[tid + off]; }
        __syncthreads();
    }
    if (tid == 0) {
        float m = s1[0] * (1.f / 25088.f);
        mu[n] = m;
        rstd[n] = rsqrtf(s2[0] * (1.f / 25088.f) - m * m + 1e-5f);
    }
}

__global__ void k_homean(const float* __restrict__ x, float* __restrict__ ho) {
    int i = blockIdx.x * 256 + threadIdx.x;
    if (i >= NN * HD) return;
    const float* b = x + (size_t)i * 49;
    float s = 0.f;
    #pragma unroll
    for (int p = 0; p < 49; p++) s += b[p];
    ho[i] = s * (1.f / 49.f);
}

__global__ void k_final(const float* __restrict__ a1t, const float* __restrict__ ho,
                        const float* __restrict__ fc2, float* __restrict__ out) {
    int n = blockIdx.x, o = threadIdx.x;
    if (o >= NCLS) return;
    const float* w = fc2 + (size_t)o * 1024;
    float s = 0.f;
    for (int c = 0; c < HD; c++) s = fmaf(a1t[(size_t)c * NN + n], w[c], s);
    const float* h = ho + (size_t)n * HD;
    for (int c = 0; c < HD; c++) s = fmaf(h[c], w[512 + c], s);
    out[(size_t)n * NCLS + o] = s;
}

extern "C" void kernel_launch(void* const* d_in, const int* in_sizes, int n_in,
                              void* d_out, int out_size) {
    const float* feat_slow = (const float*)d_in[0];
    const float* feat_fast = (const float*)d_in[1];
    const float* rois      = (const float*)d_in[2];
    const float* w_reduce  = (const float*)d_in[6];
    const float* w_conv1   = (const float*)d_in[7];
    const float* w_conv2   = (const float*)d_in[8];
    const float* wq        = (const float*)d_in[9];
    const float* wk        = (const float*)d_in[10];
    const float* wv        = (const float*)d_in[11];
    const float* wm        = (const float*)d_in[12];
    const float* gn_g      = (const float*)d_in[13];
    const float* gn_b      = (const float*)d_in[14];
    const float* fc1_w     = (const float*)d_in[15];
    const float* fc2_w     = (const float*)d_in[16];
    float* out = (float*)d_out;

    float *p_tslow, *p_tfast, *p_red, *p_actor, *p_gbase, *p_av, *p_x1, *p_x2,
          *p_x, *p_qkv, *p_virt, *p_mu, *p_rstd, *p_ho, *p_a1;
    bf *p_mTh, *p_mTl, *p_ph, *p_pl, *p_gfh, *p_gfl, *p_cEh, *p_cEl, *p_cFh, *p_cFl;
    bf *p_wrh, *p_wrl, *p_wgh, *p_wgl, *p_wc2h, *p_wc2l, *p_wqh, *p_wql, *p_wmh, *p_wml;
    cudaGetSymbolAddress((void**)&p_tslow, g_tslow);
    cudaGetSymbolAddress((void**)&p_tfast, g_tfast);
    cudaGetSymbolAddress((void**)&p_mTh,   g_meanT_h);
    cudaGetSymbolAddress((void**)&p_mTl,   g_meanT_l);
    cudaGetSymbolAddress((void**)&p_ph,    g_pool_h);
    cudaGetSymbolAddress((void**)&p_pl,    g_pool_l);
    cudaGetSymbolAddress((void**)&p_red,   g_red);
    cudaGetSymbolAddress((void**)&p_actor, g_actor);
    cudaGetSymbolAddress((void**)&p_gfh,   g_gf_h);
    cudaGetSymbolAddress((void**)&p_gfl,   g_gf_l);
    cudaGetSymbolAddress((void**)&p_gbase, g_gbase);
    cudaGetSymbolAddress((void**)&p_av,    g_av);
    cudaGetSymbolAddress((void**)&p_x1,    g_x1);
    cudaGetSymbolAddress((void**)&p_cEh,   g_colE_h);
    cudaGetSymbolAddress((void**)&p_cEl,   g_colE_l);
    cudaGetSymbolAddress((void**)&p_x2,    g_x2);
    cudaGetSymbolAddress((void**)&p_x,     g_x);
    cudaGetSymbolAddress((void**)&p_cFh,   g_colF_h);
    cudaGetSymbolAddress((void**)&p_cFl,   g_colF_l);
    cudaGetSymbolAddress((void**)&p_qkv,   g_qkv);
    cudaGetSymbolAddress((void**)&p_virt,  g_virt);
    cudaGetSymbolAddress((void**)&p_mu,    g_mu);
    cudaGetSymbolAddress((void**)&p_rstd,  g_rstd);
    cudaGetSymbolAddress((void**)&p_ho,    g_ho);
    cudaGetSymbolAddress((void**)&p_a1,    g_a1);
    cudaGetSymbolAddress((void**)&p_wrh,   g_wred_h);
    cudaGetSymbolAddress((void**)&p_wrl,   g_wred_l);
    cudaGetSymbolAddress((void**)&p_wgh,   g_wg_h);
    cudaGetSymbolAddress((void**)&p_wgl,   g_wg_l);
    cudaGetSymbolAddress((void**)&p_wc2h,  g_wc2_h);
    cudaGetSymbolAddress((void**)&p_wc2l,  g_wc2_l);
    cudaGetSymbolAddress((void**)&p_wqh,   g_wqkv_h);
    cudaGetSymbolAddress((void**)&p_wql,   g_wqkv_l);
    cudaGetSymbolAddress((void**)&p_wmh,   g_wm2_h);
    cudaGetSymbolAddress((void**)&p_wml,   g_wm2_l);

    // ---- weight splits ----
    {
        long t;
        t = (long)RD * CC;
        k_splits<<<(int)((t + 255) / 256), 256>>>(w_reduce, CC, 0, CC, t, p_wrh, p_wrl);
        t = (long)HD * RD;
        k_splits<<<(int)((t + 255) / 256), 256>>>(w_conv1, 2 * RD, 0, RD, t, p_wgh, p_wgl);
        t = (long)HD * KC;
        k_splits<<<(int)((t + 255) / 256), 256>>>(w_conv2, KC, 0, KC, t, p_wc2h, p_wc2l);
        const float* srcs[3] = {wq, wk, wv};
        for (int d = 0; d < 2; d++) {
            for (int wch = 0; wch < 3; wch++) {
                size_t doff = ((size_t)d * 3 + wch) * HD * KC;
                k_splits<<<(int)((t + 255) / 256), 256>>>(srcs[wch] + (size_t)d * HD * KC,
                                                          KC, 0, KC, t,
                                                          p_wqh + doff, p_wql + doff);
            }
            k_splits<<<(int)((t + 255) / 256), 256>>>(wm + (size_t)d * HD * KC, KC, 0, KC, t,
                                                      p_wmh + (size_t)d * HD * KC,
                                                      p_wml + (size_t)d * HD * KC);
        }
    }

    // ---- features ----
    k_transpose<<<dim3(CS / 32, 8, B_ * NS), dim3(32, 8)>>>(feat_slow, p_tslow, CS, NS);
    k_transpose<<<dim3(CF / 32, 8, B_ * NF), dim3(32, 8)>>>(feat_fast, p_tfast, CF, NF);
    k_meansplit<<<dim3(CC / 32, 8, B_), dim3(32, 8)>>>(feat_slow, feat_fast, p_mTh, p_mTl);
    k_roipool<<<dim3(49, NN), 256>>>(rois, p_tslow, p_tfast, p_ph, p_pl);

    // ---- reduce conv on pooled rois + rowmax ----
    k_tgemm<0><<<dim3(31, 8), 256>>>(p_wrh, p_wrl, p_ph, p_pl, 3920, CC,
                                     p_red, nullptr, nullptr);
    k_rowmax<<<(NN * RD + 255) / 256, 256>>>(p_red, p_actor);

    // ---- gfeat ----
    k_tgemm<4><<<dim3(16, 8), 256>>>(p_wrh, p_wrl, p_mTh, p_mTl, 2048, CC,
                                     nullptr, p_gfh, p_gfl);
    // ---- gbase ----
    k_tgemm<5><<<dim3(16, 4), 256>>>(p_wgh, p_wgl, p_gfh, p_gfl, 2048, RD,
                                     p_gbase, nullptr, nullptr);
    // ---- av ----
    k_gemm<80, 0><<<dim3(2, 4), 256>>>(w_conv1, 2 * RD, RD, p_actor, p_av, RD);
    // ---- x1 ----
    k_x1<<<(NN * HD * HW + 255) / 256, 256>>>(p_gbase, p_av, p_x1);
    // ---- conv2 ----
    k_im2col16<<<dim3(196, NN), 256>>>(p_x1, p_cEh, p_cEl);
    k_tgemm<2><<<dim3(123, 4), 256>>>(p_wc2h, p_wc2l, p_cEh, p_cEl, 15680, KC,
                                      p_x2, nullptr, nullptr);
    // ---- maxpool ----
    k_maxpool<<<(NN * HD * 49 + 255) / 256, 256>>>(p_x2, p_x);

    // ---- HR2O blocks ----
    for (int d = 0; d < 2; d++) {
        k_im2col7<<<dim3(49, NN), 256>>>(p_x, p_cFh, p_cFl);
        k_tgemm<1><<<dim3(31, 12), 256>>>(p_wqh + (size_t)d * 3 * HD * KC,
                                          p_wql + (size_t)d * 3 * HD * KC,
                                          p_cFh, p_cFl, 3920, KC,
                                          p_qkv, nullptr, nullptr);
        k_att<<<B_ * 49, 512>>>(p_qkv, p_qkv + (size_t)NN * HD * 49,
                                p_qkv + (size_t)2 * NN * HD * 49, p_virt);
        k_lnstats<<<NN, 512>>>(p_virt, p_mu, p_rstd);
        k_im2col7_ln<<<dim3(49, NN), 256>>>(p_virt, p_mu, p_rstd,
                                            gn_g + (size_t)d * HD, gn_b + (size_t)d * HD,
                                            p_cFh, p_cFl);
        k_tgemm<3><<<dim3(31, 4), 256>>>(p_wmh + (size_t)d * HD * KC,
                                         p_wml + (size_t)d * HD * KC,
                                         p_cFh, p_cFl, 3920, KC,
                                         p_x, nullptr, nullptr);
    }

    // ---- head ----
    k_homean<<<(NN * HD + 255) / 256, 256>>>(p_x, p_ho);
    k_gemm<80, 1><<<dim3(2, 4), 256>>>(fc1_w, RD, 0, p_actor, p_a1, RD);
    k_final<<<NN, 64>>>(p_a1, p_ho, fc2_w, out);
}